// round 7
// baseline (speedup 1.0000x reference)
#include <cuda_runtime.h>
#include <math.h>

#define BB 8
#define TT 2048
#define CC 384
#define HH 64

// Scratch (allocation-free rule: __device__ globals). NOTE: no P matrix anymore.
__device__ float g_q[BB * TT * HH];                 // 4 MB
__device__ float g_k[BB * TT * HH];                 // 4 MB
__device__ float g_v[BB * TT * HH];                 // 4 MB
__device__ float g_sum[BB * TT];                    // 64 KB (per-key exp sums)

// ---------------------------------------------------------------------------
// tf32 helpers
// ---------------------------------------------------------------------------
__device__ __forceinline__ unsigned f2tf(float f) {
    unsigned u;
    asm("cvt.rna.tf32.f32 %0, %1;" : "=r"(u) : "f"(f));
    return u;
}

__device__ __forceinline__ void mma8(float* c, const unsigned* a, const unsigned* b) {
    asm("mma.sync.aligned.m16n8k8.row.col.f32.tf32.tf32.f32 "
        "{%0,%1,%2,%3},{%4,%5,%6,%7},{%8,%9},{%0,%1,%2,%3};"
        : "+f"(c[0]), "+f"(c[1]), "+f"(c[2]), "+f"(c[3])
        : "r"(a[0]), "r"(a[1]), "r"(a[2]), "r"(a[3]), "r"(b[0]), "r"(b[1]));
}

// Swizzled K-major 64x64 tile: element (k, m) at [(k<<6) + (m ^ ((k&7)<<3))].
// Frag loads (k = k0+tg, m = base+g): bank = (m ^ (8*tg)) % 32 -> g ^ 8tg, all
// 32 distinct -> conflict-free. Fills: <=8-way (amortized, once per tile).
#define SW(arr, k, m) arr[((k) << 6) + ((m) ^ (((k) & 7) << 3))]

// Fragment maps (m16n8k8, .row.col), g = lane>>2, tg = lane&3:
//   A (mxk, K-major): a0=(k0+tg, m0+g) a1=(k0+tg, m0+g+8) a2=(k0+tg+4, m0+g) a3=(k0+tg+4, m0+g+8)
//   B (kxn, K-major): b0=(k0+tg, n0+g) b1=(k0+tg+4, n0+g)
//   C: rows m0+g (c0,c1), m0+g+8 (c2,c3); cols n0+2tg, n0+2tg+1

// ---------------------------------------------------------------------------
// Kernel 0: zero d_out (attn accumulates atomically) and g_sum.
// ---------------------------------------------------------------------------
__global__ void zero_kernel(float* __restrict__ out) {
    const int i = blockIdx.x * 256 + threadIdx.x;
    const float4 z = make_float4(0.f, 0.f, 0.f, 0.f);
    if (i < (BB * TT * HH) / 4) ((float4*)out)[i] = z;
    if (i < (BB * TT) / 4)      ((float4*)g_sum)[i] = z;
}

// ---------------------------------------------------------------------------
// Kernel 1: fused projections, tf32 MMA. grid = (B*T/64, 3), block = 256.
// ---------------------------------------------------------------------------
__global__ void proj_kernel(const float* __restrict__ x,
                            const float* __restrict__ Wq,
                            const float* __restrict__ Wk,
                            const float* __restrict__ Wv) {
    __shared__ unsigned xsT[32 * 64];  // [k][m] swizzled (k<32 ok: (k&7) pattern same)
    __shared__ unsigned ws[32 * 64];   // [k][n] swizzled
    const float* W  = (blockIdx.y == 0) ? Wq : (blockIdx.y == 1) ? Wk : Wv;
    float* outp     = (blockIdx.y == 0) ? g_q : (blockIdx.y == 1) ? g_k : g_v;
    const int row0 = blockIdx.x * 64;
    const int tid = threadIdx.x;
    const int lane = tid & 31, wid = tid >> 5;
    const int g = lane >> 2, tg = lane & 3;
    const int mw = (wid & 1) * 32, nw = (wid >> 1) * 16;
    float acc[2][2][4] = {};
    for (int k0c = 0; k0c < CC; k0c += 32) {
#pragma unroll
        for (int i = tid; i < 512; i += 256) {  // x: 64 rows x 32 k, transpose
            int r = i >> 3, c4 = (i & 7) * 4;
            float4 v = *(const float4*)&x[(size_t)(row0 + r) * CC + k0c + c4];
            SW(xsT, c4 + 0, r) = f2tf(v.x); SW(xsT, c4 + 1, r) = f2tf(v.y);
            SW(xsT, c4 + 2, r) = f2tf(v.z); SW(xsT, c4 + 3, r) = f2tf(v.w);
        }
#pragma unroll
        for (int i = tid; i < 512; i += 256) {  // W: 32 k x 64 n, K-major direct
            int r = i >> 4, c4 = (i & 15) * 4;
            float4 v = *(const float4*)&W[(k0c + r) * HH + c4];
            *(uint4*)&ws[(r << 6) + (c4 ^ ((r & 7) << 3))] =
                make_uint4(f2tf(v.x), f2tf(v.y), f2tf(v.z), f2tf(v.w));
        }
        __syncthreads();
#pragma unroll
        for (int kk = 0; kk < 32; kk += 8) {
            unsigned a[2][4], bq[2][2];
#pragma unroll
            for (int mt = 0; mt < 2; mt++) {
                int rb = mw + mt * 16;
                a[mt][0] = SW(xsT, kk + tg, rb + g);     a[mt][1] = SW(xsT, kk + tg, rb + g + 8);
                a[mt][2] = SW(xsT, kk + tg + 4, rb + g); a[mt][3] = SW(xsT, kk + tg + 4, rb + g + 8);
            }
#pragma unroll
            for (int nt = 0; nt < 2; nt++) {
                int cb = nw + nt * 8;
                bq[nt][0] = SW(ws, kk + tg, cb + g); bq[nt][1] = SW(ws, kk + tg + 4, cb + g);
            }
#pragma unroll
            for (int mt = 0; mt < 2; mt++)
#pragma unroll
                for (int nt = 0; nt < 2; nt++) mma8(acc[mt][nt], a[mt], bq[nt]);
        }
        __syncthreads();
    }
#pragma unroll
    for (int mt = 0; mt < 2; mt++)
#pragma unroll
        for (int rs = 0; rs < 2; rs++) {
            int row = row0 + mw + mt * 16 + rs * 8 + g;
#pragma unroll
            for (int nt = 0; nt < 2; nt++) {
                int col = nw + nt * 8 + 2 * tg;
                *(float2*)&outp[(size_t)row * HH + col] =
                    make_float2(acc[mt][nt][rs * 2], acc[mt][nt][rs * 2 + 1]);
            }
        }
}

// ---------------------------------------------------------------------------
// Kernel 2: Z[b][s] = sum_t exp(scale*k[s].q[t]) over t>=s. NO P store.
// grid = (T/64 t, T/64 s, B), block = 256.
// ---------------------------------------------------------------------------
__global__ void sumexp_kernel(float scale) {
    const int t0 = blockIdx.x * 64;
    const int s0 = blockIdx.y * 64;
    if (t0 + 63 < s0) return;
    const int b = blockIdx.z;
    __shared__ unsigned ksT[64 * 64];  // [h][s] swizzled
    __shared__ unsigned qsT[64 * 64];  // [h][t] swizzled
    const float* kb = g_k + (size_t)b * TT * HH;
    const float* qb = g_q + (size_t)b * TT * HH;
    const int tid = threadIdx.x;
#pragma unroll
    for (int i = tid; i < 1024; i += 256) {
        int r = i >> 4, c4 = (i & 15) * 4;
        float4 kv = *(const float4*)&kb[(size_t)(s0 + r) * HH + c4];
        float4 qv = *(const float4*)&qb[(size_t)(t0 + r) * HH + c4];
        SW(ksT, c4 + 0, r) = f2tf(kv.x); SW(ksT, c4 + 1, r) = f2tf(kv.y);
        SW(ksT, c4 + 2, r) = f2tf(kv.z); SW(ksT, c4 + 3, r) = f2tf(kv.w);
        SW(qsT, c4 + 0, r) = f2tf(qv.x); SW(qsT, c4 + 1, r) = f2tf(qv.y);
        SW(qsT, c4 + 2, r) = f2tf(qv.z); SW(qsT, c4 + 3, r) = f2tf(qv.w);
    }
    __syncthreads();
    const int lane = tid & 31, wid = tid >> 5;
    const int g = lane >> 2, tg = lane & 3;
    const int mw = (wid & 1) * 32, nw = (wid >> 1) * 16;
    float acc[2][2][4] = {};
#pragma unroll
    for (int k0 = 0; k0 < 64; k0 += 8) {
        unsigned a[2][4], bq[2][2];
#pragma unroll
        for (int mt = 0; mt < 2; mt++) {
            int rb = mw + mt * 16;
            a[mt][0] = SW(ksT, k0 + tg, rb + g);     a[mt][1] = SW(ksT, k0 + tg, rb + g + 8);
            a[mt][2] = SW(ksT, k0 + tg + 4, rb + g); a[mt][3] = SW(ksT, k0 + tg + 4, rb + g + 8);
        }
#pragma unroll
        for (int nt = 0; nt < 2; nt++) {
            int cb = nw + nt * 8;
            bq[nt][0] = SW(qsT, k0 + tg, cb + g); bq[nt][1] = SW(qsT, k0 + tg + 4, cb + g);
        }
#pragma unroll
        for (int mt = 0; mt < 2; mt++)
#pragma unroll
            for (int nt = 0; nt < 2; nt++) mma8(acc[mt][nt], a[mt], bq[nt]);
    }
    float* Zb = g_sum + b * TT;
#pragma unroll
    for (int mt = 0; mt < 2; mt++)
#pragma unroll
        for (int rs = 0; rs < 2; rs++) {
            const int s = s0 + mw + mt * 16 + rs * 8 + g;
            float rowsum = 0.f;
#pragma unroll
            for (int nt = 0; nt < 2; nt++) {
                const int t = t0 + nw + nt * 8 + 2 * tg;
                if (t >= s)     rowsum += __expf(acc[mt][nt][rs * 2] * scale);
                if (t + 1 >= s) rowsum += __expf(acc[mt][nt][rs * 2 + 1] * scale);
            }
            rowsum += __shfl_xor_sync(0xffffffffu, rowsum, 1);
            rowsum += __shfl_xor_sync(0xffffffffu, rowsum, 2);
            if (tg == 0) atomicAdd(&Zb[s], rowsum);
        }
}

// ---------------------------------------------------------------------------
// Kernel 3: fused scores-recompute + normalize + PV. P lives only in smem.
// grid = (T/64 t, 8 s-chunks of 4 tiles, B), block = 256.
// Smem: qsT 16K + ksPs 16K (K tile, then aliased as the P tile) + vs 16K = 48K.
// ---------------------------------------------------------------------------
__global__ void __launch_bounds__(256, 2) attn_kernel(float* __restrict__ out,
                                                      float scale) {
    const int tt = blockIdx.x;
    const int chunk0 = blockIdx.y * 4;
    if (chunk0 > tt) return;
    const int t0 = tt * 64;
    const int b = blockIdx.z;
    const float* kb = g_k + (size_t)b * TT * HH;
    const float* qb = g_q + (size_t)b * TT * HH;
    const float* vb = g_v + (size_t)b * TT * HH;
    const float* Zb = g_sum + b * TT;

    __shared__ unsigned qsT[64 * 64];   // [h][t] swizzled (A/B for scores)
    __shared__ unsigned ksPs[64 * 64];  // [h][s] for scores, then [s][t] as P
    __shared__ unsigned vs[64 * 64];    // [s][h] swizzled (B for PV, K-major in s)

    const int tid = threadIdx.x;
    const int lane = tid & 31, wid = tid >> 5;
    const int g = lane >> 2, tg = lane & 3;
    const int mw = (wid & 1) * 32, nw = (wid >> 1) * 16;

    // q tile (fixed for the block)
#pragma unroll
    for (int i = tid; i < 1024; i += 256) {
        int r = i >> 4, c4 = (i & 15) * 4;
        float4 qv = *(const float4*)&qb[(size_t)(t0 + r) * HH + c4];
        SW(qsT, c4 + 0, r) = f2tf(qv.x); SW(qsT, c4 + 1, r) = f2tf(qv.y);
        SW(qsT, c4 + 2, r) = f2tf(qv.z); SW(qsT, c4 + 3, r) = f2tf(qv.w);
    }

    float acc_o[2][2][4] = {};
    const int st_end = min(chunk0 + 4, tt + 1);
    for (int st = chunk0; st < st_end; st++) {
        const int s0 = st * 64;
        __syncthreads();  // prev PV reads done (and qsT fill on first iter)
        // fill K (transposed) and V (row-major = K-major in s)
#pragma unroll
        for (int i = tid; i < 1024; i += 256) {
            int r = i >> 4, c4 = (i & 15) * 4;
            float4 kv = *(const float4*)&kb[(size_t)(s0 + r) * HH + c4];
            SW(ksPs, c4 + 0, r) = f2tf(kv.x); SW(ksPs, c4 + 1, r) = f2tf(kv.y);
            SW(ksPs, c4 + 2, r) = f2tf(kv.z); SW(ksPs, c4 + 3, r) = f2tf(kv.w);
            float4 vv = *(const float4*)&vb[(size_t)(s0 + r) * HH + c4];
            *(uint4*)&vs[(r << 6) + (c4 ^ ((r & 7) << 3))] =
                make_uint4(f2tf(vv.x), f2tf(vv.y), f2tf(vv.z), f2tf(vv.w));
        }
        __syncthreads();

        // scores MMA: m=s, n=t, k=h
        float accs[2][2][4] = {};
#pragma unroll
        for (int k0 = 0; k0 < 64; k0 += 8) {
            unsigned a[2][4], bq[2][2];
#pragma unroll
            for (int mt = 0; mt < 2; mt++) {
                int rb = mw + mt * 16;
                a[mt][0] = SW(ksPs, k0 + tg, rb + g);     a[mt][1] = SW(ksPs, k0 + tg, rb + g + 8);
                a[mt][2] = SW(ksPs, k0 + tg + 4, rb + g); a[mt][3] = SW(ksPs, k0 + tg + 4, rb + g + 8);
            }
#pragma unroll
            for (int nt = 0; nt < 2; nt++) {
                int cb = nw + nt * 8;
                bq[nt][0] = SW(qsT, k0 + tg, cb + g); bq[nt][1] = SW(qsT, k0 + tg + 4, cb + g);
            }
#pragma unroll
            for (int mt = 0; mt < 2; mt++)
#pragma unroll
                for (int nt = 0; nt < 2; nt++) mma8(accs[mt][nt], a[mt], bq[nt]);
        }
        __syncthreads();  // all K reads done; ksPs may be overwritten as P

        // epilogue: P[s][t] = exp(score*scale)/Z[s] (0 if t<s), stored swizzled
#pragma unroll
        for (int mt = 0; mt < 2; mt++)
#pragma unroll
            for (int rs = 0; rs < 2; rs++) {
                const int s_loc = mw + mt * 16 + rs * 8 + g;  // s_loc & 7 == g
                const int s = s0 + s_loc;
                const float iz = __frcp_rn(Zb[s]);
#pragma unroll
                for (int nt = 0; nt < 2; nt++) {
                    const int t_loc = nw + nt * 8 + 2 * tg;
                    const int t = t0 + t_loc;
                    float e0 = (t >= s)     ? __expf(accs[mt][nt][rs * 2] * scale) * iz     : 0.f;
                    float e1 = (t + 1 >= s) ? __expf(accs[mt][nt][rs * 2 + 1] * scale) * iz : 0.f;
                    *(uint2*)&ksPs[(s_loc << 6) + (t_loc ^ (g << 3))] =
                        make_uint2(f2tf(e0), f2tf(e1));
                }
            }
        __syncthreads();  // P visible

        // PV MMA: m=t, n=h, k=s. A = P[s][t], B = vs[s][h]
#pragma unroll
        for (int k0 = 0; k0 < 64; k0 += 8) {
            unsigned a[2][4], bq[2][2];
#pragma unroll
            for (int mt = 0; mt < 2; mt++) {
                int rb = mw + mt * 16;
                a[mt][0] = SW(ksPs, k0 + tg, rb + g);     a[mt][1] = SW(ksPs, k0 + tg, rb + g + 8);
                a[mt][2] = SW(ksPs, k0 + tg + 4, rb + g); a[mt][3] = SW(ksPs, k0 + tg + 4, rb + g + 8);
            }
#pragma unroll
            for (int nt = 0; nt < 2; nt++) {
                int cb = nw + nt * 8;
                bq[nt][0] = SW(vs, k0 + tg, cb + g); bq[nt][1] = SW(vs, k0 + tg + 4, cb + g);
            }
#pragma unroll
            for (int mt = 0; mt < 2; mt++)
#pragma unroll
                for (int nt = 0; nt < 2; nt++) mma8(acc_o[mt][nt], a[mt], bq[nt]);
        }
    }

    float* ob = out + (size_t)b * TT * HH;
#pragma unroll
    for (int mt = 0; mt < 2; mt++)
#pragma unroll
        for (int rs = 0; rs < 2; rs++) {
            const int t = t0 + mw + mt * 16 + rs * 8 + g;
#pragma unroll
            for (int nt = 0; nt < 2; nt++) {
                const int h = nw + nt * 8 + 2 * tg;
                atomicAdd(&ob[(size_t)t * HH + h],     acc_o[mt][nt][rs * 2]);
                atomicAdd(&ob[(size_t)t * HH + h + 1], acc_o[mt][nt][rs * 2 + 1]);
            }
        }
}

// ---------------------------------------------------------------------------
extern "C" void kernel_launch(void* const* d_in, const int* in_sizes, int n_in,
                              void* d_out, int out_size) {
    const float* x  = (const float*)d_in[0];
    const float* Wq = (const float*)d_in[1];
    const float* Wk = (const float*)d_in[2];
    const float* Wv = (const float*)d_in[3];
    float* out = (float*)d_out;

    const float scale = 1.0f / sqrtf((float)CC);

    zero_kernel<<<1024, 256>>>(out);

    dim3 gProj(BB * TT / 64, 3);
    proj_kernel<<<gProj, 256>>>(x, Wq, Wk, Wv);

    dim3 gSum(TT / 64, TT / 64, BB);
    sumexp_kernel<<<gSum, 256>>>(scale);

    dim3 gAttn(TT / 64, 8, BB);
    attn_kernel<<<gAttn, 256>>>(out, scale);
}

// round 8
// speedup vs baseline: 1.0998x; 1.0998x over previous
#include <cuda_runtime.h>
#include <math.h>

#define BB 8
#define TT 2048
#define CC 384
#define HH 64

// Scratch (allocation-free rule: __device__ globals). No P matrix.
__device__ float g_q[BB * TT * HH];                 // 4 MB
__device__ float g_k[BB * TT * HH];                 // 4 MB
__device__ float g_v[BB * TT * HH];                 // 4 MB
__device__ float g_sum[BB * TT];                    // per-key exp sums
__device__ float g_inv[BB * TT];                    // reciprocals

// ---------------------------------------------------------------------------
// tf32 helpers
// ---------------------------------------------------------------------------
__device__ __forceinline__ unsigned f2tf(float f) {
    unsigned u;
    asm("cvt.rna.tf32.f32 %0, %1;" : "=r"(u) : "f"(f));
    return u;
}

__device__ __forceinline__ void mma8(float* c, const unsigned* a, const unsigned* b) {
    asm("mma.sync.aligned.m16n8k8.row.col.f32.tf32.tf32.f32 "
        "{%0,%1,%2,%3},{%4,%5,%6,%7},{%8,%9},{%0,%1,%2,%3};"
        : "+f"(c[0]), "+f"(c[1]), "+f"(c[2]), "+f"(c[3])
        : "r"(a[0]), "r"(a[1]), "r"(a[2]), "r"(a[3]), "r"(b[0]), "r"(b[1]));
}

// Swizzled K-major tiles. Width-64: (k,m) -> [(k<<6) + (m ^ ((k&7)<<3))]
// Width-128: (k,m) -> [(k<<7) + (m ^ ((k&7)<<3))]
// Frag loads conflict-free (bank = (m ^ 8tg) % 32, all 32 distinct).
#define SW(arr, k, m)  arr[((k) << 6) + ((m) ^ (((k) & 7) << 3))]
#define SW1(arr, k, m) arr[((k) << 7) + ((m) ^ (((k) & 7) << 3))]

// Fragment maps (m16n8k8 .row.col), g = lane>>2, tg = lane&3:
//   A: a0=(row g, k tg) a1=(row g+8, k tg) a2=(row g, k tg+4) a3=(row g+8, k tg+4)
//   B: b0=(k tg, col g) b1=(k tg+4, col g)
//   C: c0=(g, 2tg) c1=(g, 2tg+1) c2=(g+8, 2tg) c3=(g+8, 2tg+1)

// ---------------------------------------------------------------------------
// Kernel 0: zero d_out and g_sum.
// ---------------------------------------------------------------------------
__global__ void zero_kernel(float* __restrict__ out) {
    const int i = blockIdx.x * 256 + threadIdx.x;
    const float4 z = make_float4(0.f, 0.f, 0.f, 0.f);
    if (i < (BB * TT * HH) / 4) ((float4*)out)[i] = z;
    if (i < (BB * TT) / 4)      ((float4*)g_sum)[i] = z;
}

// ---------------------------------------------------------------------------
// Kernel 1: fused projections, tf32 MMA. grid = (B*T/64, 3), block = 256.
// (unchanged from R6 — already cheap)
// ---------------------------------------------------------------------------
__global__ void proj_kernel(const float* __restrict__ x,
                            const float* __restrict__ Wq,
                            const float* __restrict__ Wk,
                            const float* __restrict__ Wv) {
    __shared__ unsigned xsT[32 * 64];
    __shared__ unsigned ws[32 * 64];
    const float* W  = (blockIdx.y == 0) ? Wq : (blockIdx.y == 1) ? Wk : Wv;
    float* outp     = (blockIdx.y == 0) ? g_q : (blockIdx.y == 1) ? g_k : g_v;
    const int row0 = blockIdx.x * 64;
    const int tid = threadIdx.x;
    const int lane = tid & 31, wid = tid >> 5;
    const int g = lane >> 2, tg = lane & 3;
    const int mw = (wid & 1) * 32, nw = (wid >> 1) * 16;
    float acc[2][2][4] = {};
    for (int k0c = 0; k0c < CC; k0c += 32) {
#pragma unroll
        for (int i = tid; i < 512; i += 256) {
            int r = i >> 3, c4 = (i & 7) * 4;
            float4 v = *(const float4*)&x[(size_t)(row0 + r) * CC + k0c + c4];
            SW(xsT, c4 + 0, r) = f2tf(v.x); SW(xsT, c4 + 1, r) = f2tf(v.y);
            SW(xsT, c4 + 2, r) = f2tf(v.z); SW(xsT, c4 + 3, r) = f2tf(v.w);
        }
#pragma unroll
        for (int i = tid; i < 512; i += 256) {
            int r = i >> 4, c4 = (i & 15) * 4;
            float4 v = *(const float4*)&W[(k0c + r) * HH + c4];
            *(uint4*)&ws[(r << 6) + (c4 ^ ((r & 7) << 3))] =
                make_uint4(f2tf(v.x), f2tf(v.y), f2tf(v.z), f2tf(v.w));
        }
        __syncthreads();
#pragma unroll
        for (int kk = 0; kk < 32; kk += 8) {
            unsigned a[2][4], bq[2][2];
#pragma unroll
            for (int mt = 0; mt < 2; mt++) {
                int rb = mw + mt * 16;
                a[mt][0] = SW(xsT, kk + tg, rb + g);     a[mt][1] = SW(xsT, kk + tg, rb + g + 8);
                a[mt][2] = SW(xsT, kk + tg + 4, rb + g); a[mt][3] = SW(xsT, kk + tg + 4, rb + g + 8);
            }
#pragma unroll
            for (int nt = 0; nt < 2; nt++) {
                int cb = nw + nt * 8;
                bq[nt][0] = SW(ws, kk + tg, cb + g); bq[nt][1] = SW(ws, kk + tg + 4, cb + g);
            }
#pragma unroll
            for (int mt = 0; mt < 2; mt++)
#pragma unroll
                for (int nt = 0; nt < 2; nt++) mma8(acc[mt][nt], a[mt], bq[nt]);
        }
        __syncthreads();
    }
#pragma unroll
    for (int mt = 0; mt < 2; mt++)
#pragma unroll
        for (int rs = 0; rs < 2; rs++) {
            int row = row0 + mw + mt * 16 + rs * 8 + g;
#pragma unroll
            for (int nt = 0; nt < 2; nt++) {
                int col = nw + nt * 8 + 2 * tg;
                *(float2*)&outp[(size_t)row * HH + col] =
                    make_float2(acc[mt][nt][rs * 2], acc[mt][nt][rs * 2 + 1]);
            }
        }
}

// ---------------------------------------------------------------------------
// Kernel 2: Z[b][s] = sum_{t>=s} exp(scale*k[s].q[t]). 128x128 tiles, no P.
// grid = (T/128 t, T/128 s, B), block 256, dyn smem 64KB (2 blocks/SM).
// Warps: 2 s-groups (64 rows) x 4 t-groups (32 cols).
// ---------------------------------------------------------------------------
__global__ void __launch_bounds__(256, 2) sumexp_kernel(float scale) {
    const int t0 = blockIdx.x * 128;
    const int s0 = blockIdx.y * 128;
    if (t0 + 127 < s0) return;
    const int b = blockIdx.z;
    extern __shared__ __align__(16) unsigned dynsm[];
    unsigned* ks = dynsm;           // [h 64][s 128] swizzled, 8192 u
    unsigned* qs = dynsm + 8192;    // [h 64][t 128] swizzled
    const float* kb = g_k + (size_t)b * TT * HH;
    const float* qb = g_q + (size_t)b * TT * HH;
    const int tid = threadIdx.x;
#pragma unroll
    for (int i = tid; i < 2048; i += 256) {
        int r = i >> 4, c4 = (i & 15) * 4;
        float4 kv = *(const float4*)&kb[(size_t)(s0 + r) * HH + c4];
        float4 qv = *(const float4*)&qb[(size_t)(t0 + r) * HH + c4];
        SW1(ks, c4 + 0, r) = f2tf(kv.x); SW1(ks, c4 + 1, r) = f2tf(kv.y);
        SW1(ks, c4 + 2, r) = f2tf(kv.z); SW1(ks, c4 + 3, r) = f2tf(kv.w);
        SW1(qs, c4 + 0, r) = f2tf(qv.x); SW1(qs, c4 + 1, r) = f2tf(qv.y);
        SW1(qs, c4 + 2, r) = f2tf(qv.z); SW1(qs, c4 + 3, r) = f2tf(qv.w);
    }
    __syncthreads();
    const int lane = tid & 31, wid = tid >> 5;
    const int g = lane >> 2, tg = lane & 3;
    const int sw = (wid & 1) * 64, twp = (wid >> 1) * 32;
    float acc[4][4][4] = {};  // [mt(s)][nt(t)][4]
#pragma unroll
    for (int k8 = 0; k8 < 8; k8++) {
        const int k0 = k8 * 8;
        unsigned a[4][4], bq[4][2];
#pragma unroll
        for (int mt = 0; mt < 4; mt++) {
            int rb = sw + mt * 16;
            a[mt][0] = SW1(ks, k0 + tg, rb + g);     a[mt][1] = SW1(ks, k0 + tg, rb + g + 8);
            a[mt][2] = SW1(ks, k0 + tg + 4, rb + g); a[mt][3] = SW1(ks, k0 + tg + 4, rb + g + 8);
        }
#pragma unroll
        for (int nt = 0; nt < 4; nt++) {
            int cb = twp + nt * 8;
            bq[nt][0] = SW1(qs, k0 + tg, cb + g); bq[nt][1] = SW1(qs, k0 + tg + 4, cb + g);
        }
#pragma unroll
        for (int mt = 0; mt < 4; mt++)
#pragma unroll
            for (int nt = 0; nt < 4; nt++) mma8(acc[mt][nt], a[mt], bq[nt]);
    }
    float* Zb = g_sum + b * TT;
#pragma unroll
    for (int mt = 0; mt < 4; mt++)
#pragma unroll
        for (int rs = 0; rs < 2; rs++) {
            const int s = s0 + sw + mt * 16 + rs * 8 + g;
            float rowsum = 0.f;
#pragma unroll
            for (int nt = 0; nt < 4; nt++) {
                const int t = t0 + twp + nt * 8 + 2 * tg;
                if (t >= s)     rowsum += __expf(acc[mt][nt][rs * 2] * scale);
                if (t + 1 >= s) rowsum += __expf(acc[mt][nt][rs * 2 + 1] * scale);
            }
            rowsum += __shfl_xor_sync(0xffffffffu, rowsum, 1);
            rowsum += __shfl_xor_sync(0xffffffffu, rowsum, 2);
            if (tg == 0) atomicAdd(&Zb[s], rowsum);
        }
}

// ---------------------------------------------------------------------------
// Kernel 3: g_inv = 1 / g_sum.
// ---------------------------------------------------------------------------
__global__ void invsum_kernel() {
    const int i = blockIdx.x * 256 + threadIdx.x;
    if (i < BB * TT) g_inv[i] = 1.0f / g_sum[i];
}

// ---------------------------------------------------------------------------
// attn tile fill: k transposed [h][s], v direct [s][h], inv staged.
// ---------------------------------------------------------------------------
__device__ __forceinline__ void fill_tile(const float* kb, const float* vb,
                                          const float* invg,
                                          unsigned* ksb, unsigned* vsb,
                                          float* invs, int s0, int tid) {
#pragma unroll
    for (int i = tid; i < 1024; i += 256) {
        int r = i >> 4, c4 = (i & 15) * 4;
        float4 kv = *(const float4*)&kb[(size_t)(s0 + r) * HH + c4];
        SW(ksb, c4 + 0, r) = f2tf(kv.x); SW(ksb, c4 + 1, r) = f2tf(kv.y);
        SW(ksb, c4 + 2, r) = f2tf(kv.z); SW(ksb, c4 + 3, r) = f2tf(kv.w);
        float4 vv = *(const float4*)&vb[(size_t)(s0 + r) * HH + c4];
        *(uint4*)&vsb[(r << 6) + (c4 ^ ((r & 7) << 3))] =
            make_uint4(f2tf(vv.x), f2tf(vv.y), f2tf(vv.z), f2tf(vv.w));
    }
    if (tid < 16) *(float4*)&invs[tid * 4] = *(const float4*)&invg[s0 + tid * 4];
}

// ---------------------------------------------------------------------------
// Kernel 4: fused scores-recompute + normalize + PV, NO P smem round-trip.
// Scores C-frags are permuted to PV A-frags with warp shuffles.
// grid = (T/64 t, 8 s-chunks of 4 tiles, B), block 256, dyn smem 66KB.
// Warps: 4 t-groups (16 rows, q-frags in regs) x 2 s-groups (32 cols).
// One __syncthreads per s-tile (double-buffered k/v).
// ---------------------------------------------------------------------------
__global__ void __launch_bounds__(256, 2) attn_kernel(float* __restrict__ out,
                                                      float scale) {
    const int tt = blockIdx.x;
    const int chunk0 = blockIdx.y * 4;
    if (chunk0 > tt) return;
    const int t0 = tt * 64;
    const int b = blockIdx.z;
    const float* kb = g_k + (size_t)b * TT * HH;
    const float* qb = g_q + (size_t)b * TT * HH;
    const float* vb = g_v + (size_t)b * TT * HH;
    const float* invg = g_inv + b * TT;

    extern __shared__ __align__(16) unsigned dynsm[];
    unsigned* ks = dynsm;                  // 2 x 4096 u
    unsigned* vs = dynsm + 8192;           // 2 x 4096 u
    float* invs = (float*)(dynsm + 16384); // 2 x 64 f

    const int tid = threadIdx.x;
    const int lane = tid & 31, wid = tid >> 5;
    const int g = lane >> 2, tg = lane & 3;
    const int twp = (wid >> 1) * 16;       // t offset of this warp (16 rows)
    const int sw = (wid & 1) * 32;         // s offset (32 cols)

    // q fragments for the whole block, held in registers (A operand, m=t)
    unsigned qf[8][4];
    {
        const float* q0 = qb + (size_t)(t0 + twp + g) * HH;
        const float* q8 = qb + (size_t)(t0 + twp + g + 8) * HH;
#pragma unroll
        for (int k8 = 0; k8 < 8; k8++) {
            const int k0 = k8 * 8;
            qf[k8][0] = f2tf(__ldg(q0 + k0 + tg));
            qf[k8][1] = f2tf(__ldg(q8 + k0 + tg));
            qf[k8][2] = f2tf(__ldg(q0 + k0 + tg + 4));
            qf[k8][3] = f2tf(__ldg(q8 + k0 + tg + 4));
        }
    }

    float acc_o[8][4] = {};   // [h8][4]: rows t0+twp+{g,g+8}, cols h8*8+{2tg,2tg+1}
    const int st_end = min(chunk0 + 4, tt + 1);
    const int srcA = (lane & 28) | (tg >> 1);
    const int srcB = srcA + 2;
    const bool odd = tg & 1;
    const int tmax = t0 + twp + 15;

    fill_tile(kb, vb, invg, ks, vs, invs, chunk0 * 64, tid);
    for (int st = chunk0; st < st_end; st++) {
        const int buf = (st - chunk0) & 1;
        __syncthreads();  // buf ready; prev compute done
        if (st + 1 < st_end)
            fill_tile(kb, vb, invg, ks + (buf ^ 1) * 4096, vs + (buf ^ 1) * 4096,
                      invs + (buf ^ 1) * 64, (st + 1) * 64, tid);
        const int s0 = st * 64;
        unsigned* ksb = ks + buf * 4096;
        unsigned* vsb = vs + buf * 4096;
        const float* invb = invs + buf * 64;

        // scores MMA: m=t (A=q regs), n=s (B=k smem), k=h
        float accs[4][4] = {};
#pragma unroll
        for (int k8 = 0; k8 < 8; k8++) {
            const int k0 = k8 * 8;
            unsigned bq[4][2];
#pragma unroll
            for (int nt = 0; nt < 4; nt++) {
                int cb = sw + nt * 8;
                bq[nt][0] = SW(ksb, k0 + tg, cb + g);
                bq[nt][1] = SW(ksb, k0 + tg + 4, cb + g);
            }
#pragma unroll
            for (int nt = 0; nt < 4; nt++) mma8(accs[nt], qf[k8], bq[nt]);
        }

        // per 8-s-col slice: exp/mask/normalize in regs, shuffle-permute to
        // PV A-frags, accumulate PV
#pragma unroll
        for (int nt = 0; nt < 4; nt++) {
            const int sbase = s0 + sw + nt * 8;
            if (sbase > tmax) continue;  // fully masked slice (warp-uniform)
            const int sc0 = sbase + 2 * tg, sc1 = sc0 + 1;
            const float iz0 = invb[sw + nt * 8 + 2 * tg];
            const float iz1 = invb[sw + nt * 8 + 2 * tg + 1];
            const int tr0 = t0 + twp + g, tr1 = tr0 + 8;
            unsigned u0 = f2tf((tr0 >= sc0) ? __expf(accs[nt][0] * scale) * iz0 : 0.f);
            unsigned u1 = f2tf((tr0 >= sc1) ? __expf(accs[nt][1] * scale) * iz1 : 0.f);
            unsigned u2 = f2tf((tr1 >= sc0) ? __expf(accs[nt][2] * scale) * iz0 : 0.f);
            unsigned u3 = f2tf((tr1 >= sc1) ? __expf(accs[nt][3] * scale) * iz1 : 0.f);
            // permute C-frag (cols 2tg,2tg+1) -> A-frag (cols tg,tg+4)
            unsigned s0a = __shfl_sync(0xffffffffu, u0, srcA);
            unsigned s1a = __shfl_sync(0xffffffffu, u1, srcA);
            unsigned s2a = __shfl_sync(0xffffffffu, u2, srcA);
            unsigned s3a = __shfl_sync(0xffffffffu, u3, srcA);
            unsigned s0b = __shfl_sync(0xffffffffu, u0, srcB);
            unsigned s1b = __shfl_sync(0xffffffffu, u1, srcB);
            unsigned s2b = __shfl_sync(0xffffffffu, u2, srcB);
            unsigned s3b = __shfl_sync(0xffffffffu, u3, srcB);
            unsigned a[4];
            a[0] = odd ? s1a : s0a;   // (t g,   s tg)
            a[1] = odd ? s3a : s2a;   // (t g+8, s tg)
            a[2] = odd ? s1b : s0b;   // (t g,   s tg+4)
            a[3] = odd ? s3b : s2b;   // (t g+8, s tg+4)
            // PV: k-slice = these 8 s, n = h (64)
#pragma unroll
            for (int h8 = 0; h8 < 8; h8++) {
                unsigned bv[2];
                bv[0] = SW(vsb, sw + nt * 8 + tg,     h8 * 8 + g);
                bv[1] = SW(vsb, sw + nt * 8 + tg + 4, h8 * 8 + g);
                mma8(acc_o[h8], a, bv);
            }
        }
    }

    // Reduce the two s-warp partials via smem, then atomics (cross-chunk sum).
    __syncthreads();
    float* sred = (float*)dynsm;  // 4 groups x 16 rows x stride 68
    const int wg = wid >> 1;
    if (sw == 32) {
#pragma unroll
        for (int h8 = 0; h8 < 8; h8++) {
            sred[wg * 1088 + g * 68 + h8 * 8 + 2 * tg]           = acc_o[h8][0];
            sred[wg * 1088 + g * 68 + h8 * 8 + 2 * tg + 1]       = acc_o[h8][1];
            sred[wg * 1088 + (g + 8) * 68 + h8 * 8 + 2 * tg]     = acc_o[h8][2];
            sred[wg * 1088 + (g + 8) * 68 + h8 * 8 + 2 * tg + 1] = acc_o[h8][3];
        }
    }
    __syncthreads();
    if (sw == 0) {
        float* ob = out + (size_t)b * TT * HH;
        const int tr0 = t0 + twp + g, tr1 = tr0 + 8;
#pragma unroll
        for (int h8 = 0; h8 < 8; h8++) {
            const int h = h8 * 8 + 2 * tg;
            atomicAdd(&ob[(size_t)tr0 * HH + h],
                      acc_o[h8][0] + sred[wg * 1088 + g * 68 + h]);
            atomicAdd(&ob[(size_t)tr0 * HH + h + 1],
                      acc_o[h8][1] + sred[wg * 1088 + g * 68 + h + 1]);
            atomicAdd(&ob[(size_t)tr1 * HH + h],
                      acc_o[h8][2] + sred[wg * 1088 + (g + 8) * 68 + h]);
            atomicAdd(&ob[(size_t)tr1 * HH + h + 1],
                      acc_o[h8][3] + sred[wg * 1088 + (g + 8) * 68 + h + 1]);
        }
    }
}

// ---------------------------------------------------------------------------
extern "C" void kernel_launch(void* const* d_in, const int* in_sizes, int n_in,
                              void* d_out, int out_size) {
    const float* x  = (const float*)d_in[0];
    const float* Wq = (const float*)d_in[1];
    const float* Wk = (const float*)d_in[2];
    const float* Wv = (const float*)d_in[3];
    float* out = (float*)d_out;

    const float scale = 1.0f / sqrtf((float)CC);

    cudaFuncSetAttribute(sumexp_kernel,
                         cudaFuncAttributeMaxDynamicSharedMemorySize, 65536);
    cudaFuncSetAttribute(attn_kernel,
                         cudaFuncAttributeMaxDynamicSharedMemorySize, 66560);

    zero_kernel<<<1024, 256>>>(out);

    dim3 gProj(BB * TT / 64, 3);
    proj_kernel<<<gProj, 256>>>(x, Wq, Wk, Wv);

    dim3 gSum(TT / 128, TT / 128, BB);
    sumexp_kernel<<<gSum, 256, 65536>>>(scale);

    invsum_kernel<<<64, 256>>>();

    dim3 gAttn(TT / 64, 8, BB);
    attn_kernel<<<gAttn, 256, 66560>>>(out, scale);
}

// round 9
// speedup vs baseline: 2.2201x; 2.0187x over previous
#include <cuda_runtime.h>
#include <cuda_fp16.h>
#include <math.h>

#define BB 8
#define TT 2048
#define CC 384
#define HH 64

// Scratch (allocation-free rule: __device__ globals)
__device__ __half g_qh[BB * TT * HH];               // 2 MB  [b][t][h]
__device__ __half g_kh[BB * TT * HH];               // 2 MB  [b][s][h]
__device__ __half g_vT[BB * HH * TT];               // 2 MB  [b][h][s] (later scaled by 1/Z)
__device__ float  g_sum[BB * TT];                   // per-key exp sums
__device__ float  g_inv[BB * TT];                   // reciprocals
__device__ __half g_Ph[(size_t)BB * TT * TT];       // 67 MB unnormalized exp, [b][t][s]

// ---------------------------------------------------------------------------
// MMA helpers
// ---------------------------------------------------------------------------
__device__ __forceinline__ unsigned f2tf(float f) {
    unsigned u;
    asm("cvt.rna.tf32.f32 %0, %1;" : "=r"(u) : "f"(f));
    return u;
}

__device__ __forceinline__ void mma8(float* c, const unsigned* a, const unsigned* b) {
    asm("mma.sync.aligned.m16n8k8.row.col.f32.tf32.tf32.f32 "
        "{%0,%1,%2,%3},{%4,%5,%6,%7},{%8,%9},{%0,%1,%2,%3};"
        : "+f"(c[0]), "+f"(c[1]), "+f"(c[2]), "+f"(c[3])
        : "r"(a[0]), "r"(a[1]), "r"(a[2]), "r"(a[3]), "r"(b[0]), "r"(b[1]));
}

// fp16 m16n8k16, fp32 accumulate. g = lane>>2, tg = lane&3.
//  A (row-major, k contiguous): a0={A[g][2tg],A[g][2tg+1]} a1=rows g+8
//                               a2={A[g][2tg+8],..} a3=rows g+8 cols +8
//  B (col-major [n][k], k contiguous): b0={B[2tg][g],B[2tg+1][g]} b1=k+8
//  C: c0=(g,2tg) c1=(g,2tg+1) c2=(g+8,2tg) c3=(g+8,2tg+1)
__device__ __forceinline__ void mma16(float* c, const unsigned* a, const unsigned* b) {
    asm("mma.sync.aligned.m16n8k16.row.col.f32.f16.f16.f32 "
        "{%0,%1,%2,%3},{%4,%5,%6,%7},{%8,%9},{%0,%1,%2,%3};"
        : "+f"(c[0]), "+f"(c[1]), "+f"(c[2]), "+f"(c[3])
        : "r"(a[0]), "r"(a[1]), "r"(a[2]), "r"(a[3]), "r"(b[0]), "r"(b[1]));
}

// tf32 swizzled tile (proj only)
#define SW(arr, k, m)  arr[((k) << 6) + ((m) ^ (((k) & 7) << 3))]

// half tiles: row stride 72 halves (144B). frag half2 load bank = (4*row + tg
// + const) % 32 over the warp -> conflict-free.
#define HS 72

// ---------------------------------------------------------------------------
// Kernel 0: zero d_out (pv accumulates atomically) and g_sum.
// ---------------------------------------------------------------------------
__global__ void zero_kernel(float* __restrict__ out) {
    const int i = blockIdx.x * 256 + threadIdx.x;
    const float4 z = make_float4(0.f, 0.f, 0.f, 0.f);
    if (i < (BB * TT * HH) / 4) ((float4*)out)[i] = z;
    if (i < (BB * TT) / 4)      ((float4*)g_sum)[i] = z;
}

// ---------------------------------------------------------------------------
// Kernel 1: fused projections, tf32 MMA (inputs are fp32). Outputs fp16:
// q -> g_qh[t][h], k -> g_kh[s][h], v -> g_vT[h][s] (transposed).
// grid = (B*T/64, 3), block = 256.
// ---------------------------------------------------------------------------
__global__ void proj_kernel(const float* __restrict__ x,
                            const float* __restrict__ Wq,
                            const float* __restrict__ Wk,
                            const float* __restrict__ Wv) {
    __shared__ unsigned xsT[32 * 64];
    __shared__ unsigned ws[32 * 64];
    const float* W = (blockIdx.y == 0) ? Wq : (blockIdx.y == 1) ? Wk : Wv;
    const int row0 = blockIdx.x * 64;
    const int tid = threadIdx.x;
    const int lane = tid & 31, wid = tid >> 5;
    const int g = lane >> 2, tg = lane & 3;
    const int mw = (wid & 1) * 32, nw = (wid >> 1) * 16;
    float acc[2][2][4] = {};
    for (int k0c = 0; k0c < CC; k0c += 32) {
#pragma unroll
        for (int i = tid; i < 512; i += 256) {
            int r = i >> 3, c4 = (i & 7) * 4;
            float4 v = *(const float4*)&x[(size_t)(row0 + r) * CC + k0c + c4];
            SW(xsT, c4 + 0, r) = f2tf(v.x); SW(xsT, c4 + 1, r) = f2tf(v.y);
            SW(xsT, c4 + 2, r) = f2tf(v.z); SW(xsT, c4 + 3, r) = f2tf(v.w);
        }
#pragma unroll
        for (int i = tid; i < 512; i += 256) {
            int r = i >> 4, c4 = (i & 15) * 4;
            float4 v = *(const float4*)&W[(k0c + r) * HH + c4];
            *(uint4*)&ws[(r << 6) + (c4 ^ ((r & 7) << 3))] =
                make_uint4(f2tf(v.x), f2tf(v.y), f2tf(v.z), f2tf(v.w));
        }
        __syncthreads();
#pragma unroll
        for (int kk = 0; kk < 32; kk += 8) {
            unsigned a[2][4], bq[2][2];
#pragma unroll
            for (int mt = 0; mt < 2; mt++) {
                int rb = mw + mt * 16;
                a[mt][0] = SW(xsT, kk + tg, rb + g);     a[mt][1] = SW(xsT, kk + tg, rb + g + 8);
                a[mt][2] = SW(xsT, kk + tg + 4, rb + g); a[mt][3] = SW(xsT, kk + tg + 4, rb + g + 8);
            }
#pragma unroll
            for (int nt = 0; nt < 2; nt++) {
                int cb = nw + nt * 8;
                bq[nt][0] = SW(ws, kk + tg, cb + g); bq[nt][1] = SW(ws, kk + tg + 4, cb + g);
            }
#pragma unroll
            for (int mt = 0; mt < 2; mt++)
#pragma unroll
                for (int nt = 0; nt < 2; nt++) mma8(acc[mt][nt], a[mt], bq[nt]);
        }
        __syncthreads();
    }
    __half* outqk = (blockIdx.y == 0) ? g_qh : g_kh;
#pragma unroll
    for (int mt = 0; mt < 2; mt++)
#pragma unroll
        for (int rs = 0; rs < 2; rs++) {
            const int row = row0 + mw + mt * 16 + rs * 8 + g;
#pragma unroll
            for (int nt = 0; nt < 2; nt++) {
                const int col = nw + nt * 8 + 2 * tg;
                const float v0 = acc[mt][nt][rs * 2], v1 = acc[mt][nt][rs * 2 + 1];
                if (blockIdx.y < 2) {
                    *(__half2*)&outqk[(size_t)row * HH + col] = __floats2half2_rn(v0, v1);
                } else {
                    const int s = row & (TT - 1);
                    const size_t hb = (size_t)(row >> 11) * HH;
                    g_vT[(hb + col) * TT + s]     = __float2half(v0);
                    g_vT[(hb + col + 1) * TT + s] = __float2half(v1);
                }
            }
        }
}

// ---------------------------------------------------------------------------
// Kernel 2: scores, fp16 MMA, 128x128 tiles. Writes P[t][s] = exp(score) (half,
// 0 where t<s) and accumulates Z[s] = sum_t exp. m = t, n = s, k = h.
// grid = (T/128 t, T/128 s, B), block 256, dyn smem 36864B (2 blocks/SM).
// Warps: 2 t-groups (64 rows) x 4 s-groups (32 cols).
// ---------------------------------------------------------------------------
__global__ void __launch_bounds__(256, 2) scores_kernel(float scale) {
    const int t0 = blockIdx.x * 128;
    const int s0 = blockIdx.y * 128;
    if (t0 + 127 < s0) return;
    const int b = blockIdx.z;
    extern __shared__ __align__(16) __half sm[];
    __half* qs = sm;              // [128][HS]
    __half* ks = sm + 128 * HS;   // [128][HS]
    const __half* qb = g_qh + (size_t)b * TT * HH;
    const __half* kb = g_kh + (size_t)b * TT * HH;
    const int tid = threadIdx.x;
#pragma unroll
    for (int i = tid; i < 1024; i += 256) {
        int r = i >> 3, j = (i & 7) * 8;
        *(uint4*)&qs[r * HS + j] = *(const uint4*)&qb[(size_t)(t0 + r) * HH + j];
        *(uint4*)&ks[r * HS + j] = *(const uint4*)&kb[(size_t)(s0 + r) * HH + j];
    }
    __syncthreads();
    const int lane = tid & 31, wid = tid >> 5;
    const int g = lane >> 2, tg = lane & 3;
    const int tw = (wid & 1) * 64, sw = (wid >> 1) * 32;
    float acc[4][4][4] = {};  // [mt(t)][nt(s)][4]
#pragma unroll
    for (int k0 = 0; k0 < 64; k0 += 16) {
        unsigned a[4][4], bq[4][2];
#pragma unroll
        for (int mt = 0; mt < 4; mt++) {
            const int r = tw + mt * 16 + g;
            a[mt][0] = *(const unsigned*)&qs[r * HS + k0 + 2 * tg];
            a[mt][1] = *(const unsigned*)&qs[(r + 8) * HS + k0 + 2 * tg];
            a[mt][2] = *(const unsigned*)&qs[r * HS + k0 + 2 * tg + 8];
            a[mt][3] = *(const unsigned*)&qs[(r + 8) * HS + k0 + 2 * tg + 8];
        }
#pragma unroll
        for (int nt = 0; nt < 4; nt++) {
            const int r = sw + nt * 8 + g;
            bq[nt][0] = *(const unsigned*)&ks[r * HS + k0 + 2 * tg];
            bq[nt][1] = *(const unsigned*)&ks[r * HS + k0 + 2 * tg + 8];
        }
#pragma unroll
        for (int mt = 0; mt < 4; mt++)
#pragma unroll
            for (int nt = 0; nt < 4; nt++) mma16(acc[mt][nt], a[mt], bq[nt]);
    }
    __half* Pb = g_Ph + (size_t)b * TT * TT;
    float* Zb = g_sum + b * TT;
    float zc[4][2] = {};
#pragma unroll
    for (int mt = 0; mt < 4; mt++)
#pragma unroll
        for (int rs = 0; rs < 2; rs++) {
            const int t = t0 + tw + mt * 16 + rs * 8 + g;
#pragma unroll
            for (int nt = 0; nt < 4; nt++) {
                const int s = s0 + sw + nt * 8 + 2 * tg;
                float e0 = (t >= s) ? __expf(acc[mt][nt][rs * 2] * scale)     : 0.f;
                float e1 = (t >  s) ? __expf(acc[mt][nt][rs * 2 + 1] * scale) : 0.f;
                *(__half2*)&Pb[(size_t)t * TT + s] = __floats2half2_rn(e0, e1);
                zc[nt][0] += e0; zc[nt][1] += e1;
            }
        }
#pragma unroll
    for (int nt = 0; nt < 4; nt++) {
        float z0 = zc[nt][0], z1 = zc[nt][1];
#pragma unroll
        for (int o = 4; o < 32; o <<= 1) {
            z0 += __shfl_xor_sync(0xffffffffu, z0, o);
            z1 += __shfl_xor_sync(0xffffffffu, z1, o);
        }
        if (g == 0) {
            const int s = s0 + sw + nt * 8 + 2 * tg;
            atomicAdd(&Zb[s], z0);
            atomicAdd(&Zb[s + 1], z1);
        }
    }
}

// ---------------------------------------------------------------------------
// Kernel 3: g_inv = 1 / g_sum.
// ---------------------------------------------------------------------------
__global__ void invsum_kernel() {
    const int i = blockIdx.x * 256 + threadIdx.x;
    if (i < BB * TT) g_inv[i] = 1.0f / g_sum[i];
}

// ---------------------------------------------------------------------------
// Kernel 4: scale vT in place by 1/Z[s]. grid = 512, block = 256 (uint4 each).
// ---------------------------------------------------------------------------
__global__ void normalize_kernel() {
    const int u = blockIdx.x * 256 + threadIdx.x;   // uint4 index
    const int hl = u * 8;
    const int bh = hl >> 11;           // b*64 + h
    const int s = hl & (TT - 1);
    const float* inv = g_inv + ((bh >> 6) << 11) + s;
    uint4 val = *(uint4*)&g_vT[(size_t)bh * TT + s];
    __half2* hp = (__half2*)&val;
    const float4 i0 = *(const float4*)&inv[0];
    const float4 i1 = *(const float4*)&inv[4];
    float2 f;
    f = __half22float2(hp[0]); hp[0] = __floats2half2_rn(f.x * i0.x, f.y * i0.y);
    f = __half22float2(hp[1]); hp[1] = __floats2half2_rn(f.x * i0.z, f.y * i0.w);
    f = __half22float2(hp[2]); hp[2] = __floats2half2_rn(f.x * i1.x, f.y * i1.y);
    f = __half22float2(hp[3]); hp[3] = __floats2half2_rn(f.x * i1.z, f.y * i1.w);
    *(uint4*)&g_vT[(size_t)bh * TT + s] = val;
}

// ---------------------------------------------------------------------------
// pv tile fill: pure uint4 copies (no conversion).
// ---------------------------------------------------------------------------
__device__ __forceinline__ void fill_pv(const __half* __restrict__ Pb,
                                        const __half* __restrict__ vTb,
                                        __half* Psb, __half* vsb,
                                        int t0, int s0, int tid) {
#pragma unroll
    for (int i = tid; i < 512; i += 256) {
        int r = i >> 3, j = (i & 7) * 8;
        *(uint4*)&Psb[r * HS + j] = *(const uint4*)&Pb[(size_t)(t0 + r) * TT + s0 + j];
        *(uint4*)&vsb[r * HS + j] = *(const uint4*)&vTb[(size_t)r * TT + s0 + j];
    }
}

// ---------------------------------------------------------------------------
// Kernel 5: out[t][h] += sum_s P[t][s] * vT[h][s] (vT pre-scaled by 1/Z).
// fp16 MMA m16n8k16: A = P (row-major), B = vT (col-major [h][s]).
// grid = (T/64 t, 8 s-chunks of 4 tiles, B), block 256, dyn smem 36864B.
// Warps: 4 t-groups (16 rows) x 2 h-groups (32 cols). Double buffered.
// ---------------------------------------------------------------------------
__global__ void __launch_bounds__(256, 2) pv_kernel(float* __restrict__ out) {
    const int tt = blockIdx.x;
    const int chunk0 = blockIdx.y * 4;
    if (chunk0 > tt) return;
    const int t0 = tt * 64;
    const int b = blockIdx.z;
    const __half* Pb = g_Ph + (size_t)b * TT * TT;
    const __half* vTb = g_vT + (size_t)b * HH * TT;
    extern __shared__ __align__(16) __half sm[];
    __half* Ps = sm;              // 2 x [64][HS]
    __half* vs = sm + 2 * 64 * HS;
    const int tid = threadIdx.x;
    const int lane = tid & 31, wid = tid >> 5;
    const int g = lane >> 2, tg = lane & 3;
    const int tw = (wid >> 1) * 16;
    const int hw = (wid & 1) * 32;
    float acc[4][4] = {};  // [nt(h)][4]
    const int st_end = min(chunk0 + 4, tt + 1);

    fill_pv(Pb, vTb, Ps, vs, t0, chunk0 * 64, tid);
    for (int st = chunk0; st < st_end; st++) {
        const int buf = (st - chunk0) & 1;
        __syncthreads();
        if (st + 1 < st_end)
            fill_pv(Pb, vTb, Ps + (buf ^ 1) * 64 * HS, vs + (buf ^ 1) * 64 * HS,
                    t0, (st + 1) * 64, tid);
        const __half* Psb = Ps + buf * 64 * HS;
        const __half* vsb = vs + buf * 64 * HS;
#pragma unroll
        for (int k0 = 0; k0 < 64; k0 += 16) {
            unsigned a[4];
            const int r = tw + g;
            a[0] = *(const unsigned*)&Psb[r * HS + k0 + 2 * tg];
            a[1] = *(const unsigned*)&Psb[(r + 8) * HS + k0 + 2 * tg];
            a[2] = *(const unsigned*)&Psb[r * HS + k0 + 2 * tg + 8];
            a[3] = *(const unsigned*)&Psb[(r + 8) * HS + k0 + 2 * tg + 8];
#pragma unroll
            for (int nt = 0; nt < 4; nt++) {
                unsigned bv[2];
                const int hr = hw + nt * 8 + g;
                bv[0] = *(const unsigned*)&vsb[hr * HS + k0 + 2 * tg];
                bv[1] = *(const unsigned*)&vsb[hr * HS + k0 + 2 * tg + 8];
                mma16(acc[nt], a, bv);
            }
        }
    }

    float* ob = out + (size_t)b * TT * HH;
    const int tr0 = t0 + tw + g, tr1 = tr0 + 8;
#pragma unroll
    for (int nt = 0; nt < 4; nt++) {
        const int h = hw + nt * 8 + 2 * tg;
        atomicAdd(&ob[(size_t)tr0 * HH + h],     acc[nt][0]);
        atomicAdd(&ob[(size_t)tr0 * HH + h + 1], acc[nt][1]);
        atomicAdd(&ob[(size_t)tr1 * HH + h],     acc[nt][2]);
        atomicAdd(&ob[(size_t)tr1 * HH + h + 1], acc[nt][3]);
    }
}

// ---------------------------------------------------------------------------
extern "C" void kernel_launch(void* const* d_in, const int* in_sizes, int n_in,
                              void* d_out, int out_size) {
    const float* x  = (const float*)d_in[0];
    const float* Wq = (const float*)d_in[1];
    const float* Wk = (const float*)d_in[2];
    const float* Wv = (const float*)d_in[3];
    float* out = (float*)d_out;

    const float scale = 1.0f / sqrtf((float)CC);

    cudaFuncSetAttribute(scores_kernel,
                         cudaFuncAttributeMaxDynamicSharedMemorySize, 36864);
    cudaFuncSetAttribute(pv_kernel,
                         cudaFuncAttributeMaxDynamicSharedMemorySize, 36864);

    zero_kernel<<<1024, 256>>>(out);

    dim3 gProj(BB * TT / 64, 3);
    proj_kernel<<<gProj, 256>>>(x, Wq, Wk, Wv);

    dim3 gScores(TT / 128, TT / 128, BB);
    scores_kernel<<<gScores, 256, 36864>>>(scale);

    invsum_kernel<<<64, 256>>>();

    normalize_kernel<<<512, 256>>>();

    dim3 gPV(TT / 64, 8, BB);
    pv_kernel<<<gPV, 256, 36864>>>(out);
}

// round 10
// speedup vs baseline: 2.4130x; 1.0869x over previous
#include <cuda_runtime.h>
#include <cuda_fp16.h>
#include <math.h>

#define BB 8
#define TT 2048
#define CC 384
#define HH 64

// Scratch (allocation-free rule: __device__ globals)
__device__ __half g_qh[BB * TT * HH];               // 2 MB  [b][t][h]
__device__ __half g_kh[BB * TT * HH];               // 2 MB  [b][s][h]
__device__ __half g_vT[BB * HH * TT];               // 2 MB  [b][h][s], later scaled 1/Z
__device__ float  g_sum[BB * TT];                   // per-key exp sums
__device__ __half g_Ph[(size_t)BB * TT * TT];       // 67 MB unnormalized exp, [b][t][s]

// ---------------------------------------------------------------------------
// fp16 m16n8k16 MMA + ldmatrix helpers. g = lane>>2, tg = lane&3.
//  A row-major [m][k]: a0=(g,2tg) a1=(g+8,2tg) a2=(g,2tg+8) a3=(g+8,2tg+8)
//  B col-major [n][k]: b0=(n g, k 2tg) b1=(n g, k 2tg+8)
//  C: c0=(g,2tg) c1=(g,2tg+1) c2=(g+8,2tg) c3=(g+8,2tg+1)
// ---------------------------------------------------------------------------
__device__ __forceinline__ void mma16(float* c, const unsigned* a, const unsigned* b) {
    asm("mma.sync.aligned.m16n8k16.row.col.f32.f16.f16.f32 "
        "{%0,%1,%2,%3},{%4,%5,%6,%7},{%8,%9},{%0,%1,%2,%3};"
        : "+f"(c[0]), "+f"(c[1]), "+f"(c[2]), "+f"(c[3])
        : "r"(a[0]), "r"(a[1]), "r"(a[2]), "r"(a[3]), "r"(b[0]), "r"(b[1]));
}

__device__ __forceinline__ void ldsm_x4(unsigned* r, unsigned addr) {
    asm volatile("ldmatrix.sync.aligned.m8n8.x4.shared.b16 {%0,%1,%2,%3}, [%4];"
                 : "=r"(r[0]), "=r"(r[1]), "=r"(r[2]), "=r"(r[3]) : "r"(addr));
}

__device__ __forceinline__ unsigned smaddr(const void* p) {
    return (unsigned)__cvta_generic_to_shared(p);
}

// A-operand x4 base (16 rows x 16 k): matrices (r0,k0),(r+8,k0),(r0,k+8),(r+8,k+8)
#define A_OFF(lane) ((((lane) & 7) + (((lane) >> 3) & 1) * 8) )
#define A_KOFF(lane) ((((lane) >> 4) & 1) * 8)
// B-operand x4 base (16 n-rows x 16 k): matrices (n0,k0),(n0,k+8),(n+8,k0),(n+8,k+8)
#define B_OFF(lane) ((((lane) & 7) + (((lane) >> 4) & 1) * 8))
#define B_KOFF(lane) ((((lane) >> 3) & 1) * 8)

#define HS 72   // half stride for 64-col k tiles (144 B rows, 16B aligned, cf)
#define PS 40   // half stride for 32-col k tiles (80 B rows, 16B aligned, cf)

// ---------------------------------------------------------------------------
// Kernel 0: zero d_out (pv accumulates atomically) and g_sum.
// ---------------------------------------------------------------------------
__global__ void zero_kernel(float* __restrict__ out) {
    const int i = blockIdx.x * 256 + threadIdx.x;
    const float4 z = make_float4(0.f, 0.f, 0.f, 0.f);
    if (i < (BB * TT * HH) / 4) ((float4*)out)[i] = z;
    if (i < (BB * TT) / 4)      ((float4*)g_sum)[i] = z;
}

// ---------------------------------------------------------------------------
// Kernel 1: fused projections, fp16 MMA (convert f32->f16 in the smem fill).
// q -> g_qh[t][h], k -> g_kh[s][h], v -> g_vT[h][s] (transposed).
// grid = (B*T/64, 3), block = 256. Warps 2(m)x4(n), warp tile 32x16.
// ---------------------------------------------------------------------------
__global__ void proj_kernel(const float* __restrict__ x,
                            const float* __restrict__ Wq,
                            const float* __restrict__ Wk,
                            const float* __restrict__ Wv) {
    __shared__ __align__(16) __half xs[64 * PS];  // [m][k32]
    __shared__ __align__(16) __half ws[64 * PS];  // [n][k32] (W transposed)
    const float* W = (blockIdx.y == 0) ? Wq : (blockIdx.y == 1) ? Wk : Wv;
    const int row0 = blockIdx.x * 64;
    const int tid = threadIdx.x;
    const int lane = tid & 31, wid = tid >> 5;
    const int g = lane >> 2, tg = lane & 3;
    const int mw = (wid & 1) * 32, nw = (wid >> 1) * 16;

    unsigned aab[2], bab;
    {
        const int ar = A_OFF(lane), ak = A_KOFF(lane);
        aab[0] = smaddr(&xs[(mw + ar) * PS + ak]);
        aab[1] = smaddr(&xs[(mw + 16 + ar) * PS + ak]);
        bab = smaddr(&ws[(nw + B_OFF(lane)) * PS + B_KOFF(lane)]);
    }

    float acc[2][2][4] = {};
    for (int k0c = 0; k0c < CC; k0c += 32) {
#pragma unroll
        for (int i = tid; i < 512; i += 256) {   // x: 64 m x 32 k
            int r = i >> 3, c4 = (i & 7) * 4;
            float4 v = *(const float4*)&x[(size_t)(row0 + r) * CC + k0c + c4];
            *(__half2*)&xs[r * PS + c4]     = __floats2half2_rn(v.x, v.y);
            *(__half2*)&xs[r * PS + c4 + 2] = __floats2half2_rn(v.z, v.w);
        }
#pragma unroll
        for (int i = tid; i < 512; i += 256) {   // W: 32 k x 64 n -> transpose
            int r = i >> 4, c4 = (i & 15) * 4;
            float4 v = *(const float4*)&W[(k0c + r) * HH + c4];
            ws[(c4 + 0) * PS + r] = __float2half(v.x);
            ws[(c4 + 1) * PS + r] = __float2half(v.y);
            ws[(c4 + 2) * PS + r] = __float2half(v.z);
            ws[(c4 + 3) * PS + r] = __float2half(v.w);
        }
        __syncthreads();
#pragma unroll
        for (int kk = 0; kk < 2; kk++) {         // two k16 steps
            unsigned a[2][4], bq[4];
            ldsm_x4(a[0], aab[0] + kk * 32);
            ldsm_x4(a[1], aab[1] + kk * 32);
            ldsm_x4(bq, bab + kk * 32);          // r0,r1 = nt0; r2,r3 = nt1
#pragma unroll
            for (int mt = 0; mt < 2; mt++)
#pragma unroll
                for (int nt = 0; nt < 2; nt++)
                    mma16(acc[mt][nt], a[mt], bq + nt * 2);
        }
        __syncthreads();
    }

    __half* outqk = (blockIdx.y == 0) ? g_qh : g_kh;
#pragma unroll
    for (int mt = 0; mt < 2; mt++)
#pragma unroll
        for (int rs = 0; rs < 2; rs++) {
            const int row = row0 + mw + mt * 16 + rs * 8 + g;
#pragma unroll
            for (int nt = 0; nt < 2; nt++) {
                const int col = nw + nt * 8 + 2 * tg;
                const float v0 = acc[mt][nt][rs * 2], v1 = acc[mt][nt][rs * 2 + 1];
                if (blockIdx.y < 2) {
                    *(__half2*)&outqk[(size_t)row * HH + col] = __floats2half2_rn(v0, v1);
                } else {
                    const int s = row & (TT - 1);
                    const size_t hb = (size_t)(row >> 11) * HH;
                    g_vT[(hb + col) * TT + s]     = __float2half(v0);
                    g_vT[(hb + col + 1) * TT + s] = __float2half(v1);
                }
            }
        }
}

// ---------------------------------------------------------------------------
// Kernel 2: scores, fp16 MMA + ldmatrix, 128x128 tiles. P[t][s] = exp (half,
// 0 where t<s); Z[s] += row sums. m=t, n=s, k=h.
// grid = (T/128, T/128, B), block 256, dyn smem 36864B (2 blocks/SM).
// Warps: 2 t-groups (64 rows) x 4 s-groups (32 cols).
// ---------------------------------------------------------------------------
__global__ void __launch_bounds__(256, 2) scores_kernel(float scale) {
    const int t0 = blockIdx.x * 128;
    const int s0 = blockIdx.y * 128;
    if (t0 + 127 < s0) return;
    const int b = blockIdx.z;
    extern __shared__ __align__(16) __half sm[];
    __half* qs = sm;              // [128][HS]
    __half* ks = sm + 128 * HS;   // [128][HS]
    const __half* qb = g_qh + (size_t)b * TT * HH;
    const __half* kb = g_kh + (size_t)b * TT * HH;
    const int tid = threadIdx.x;
#pragma unroll
    for (int i = tid; i < 1024; i += 256) {
        int r = i >> 3, j = (i & 7) * 8;
        *(uint4*)&qs[r * HS + j] = *(const uint4*)&qb[(size_t)(t0 + r) * HH + j];
        *(uint4*)&ks[r * HS + j] = *(const uint4*)&kb[(size_t)(s0 + r) * HH + j];
    }
    __syncthreads();
    const int lane = tid & 31, wid = tid >> 5;
    const int g = lane >> 2, tg = lane & 3;
    const int tw = (wid & 1) * 64, sw = (wid >> 1) * 32;

    unsigned aab[4], bab[2];
    {
        const int ar = A_OFF(lane), ak = A_KOFF(lane);
        const int br = B_OFF(lane), bk = B_KOFF(lane);
#pragma unroll
        for (int mt = 0; mt < 4; mt++)
            aab[mt] = smaddr(&qs[(tw + mt * 16 + ar) * HS + ak]);
#pragma unroll
        for (int np = 0; np < 2; np++)
            bab[np] = smaddr(&ks[(sw + np * 16 + br) * HS + bk]);
    }

    float acc[4][4][4] = {};  // [mt(t)][nt(s)][4]
#pragma unroll
    for (int k4 = 0; k4 < 4; k4++) {
        unsigned a[4][4], bq[2][4];
#pragma unroll
        for (int mt = 0; mt < 4; mt++) ldsm_x4(a[mt], aab[mt] + k4 * 32);
#pragma unroll
        for (int np = 0; np < 2; np++) ldsm_x4(bq[np], bab[np] + k4 * 32);
#pragma unroll
        for (int mt = 0; mt < 4; mt++)
#pragma unroll
            for (int nt = 0; nt < 4; nt++)
                mma16(acc[mt][nt], a[mt], bq[nt >> 1] + (nt & 1) * 2);
    }

    __half* Pb = g_Ph + (size_t)b * TT * TT;
    float* Zb = g_sum + b * TT;
    float zc[4][2] = {};
#pragma unroll
    for (int mt = 0; mt < 4; mt++)
#pragma unroll
        for (int rs = 0; rs < 2; rs++) {
            const int t = t0 + tw + mt * 16 + rs * 8 + g;
#pragma unroll
            for (int nt = 0; nt < 4; nt++) {
                const int s = s0 + sw + nt * 8 + 2 * tg;
                float e0 = (t >= s) ? __expf(acc[mt][nt][rs * 2] * scale)     : 0.f;
                float e1 = (t >  s) ? __expf(acc[mt][nt][rs * 2 + 1] * scale) : 0.f;
                *(__half2*)&Pb[(size_t)t * TT + s] = __floats2half2_rn(e0, e1);
                zc[nt][0] += e0; zc[nt][1] += e1;
            }
        }
#pragma unroll
    for (int nt = 0; nt < 4; nt++) {
        float z0 = zc[nt][0], z1 = zc[nt][1];
#pragma unroll
        for (int o = 4; o < 32; o <<= 1) {
            z0 += __shfl_xor_sync(0xffffffffu, z0, o);
            z1 += __shfl_xor_sync(0xffffffffu, z1, o);
        }
        if (g == 0) {
            const int s = s0 + sw + nt * 8 + 2 * tg;
            atomicAdd(&Zb[s], z0);
            atomicAdd(&Zb[s + 1], z1);
        }
    }
}

// ---------------------------------------------------------------------------
// Kernel 3: scale vT in place by 1/Z[s] (rcp computed here; no inv array).
// grid = 512, block = 256 (one uint4 = 8 halves per thread).
// ---------------------------------------------------------------------------
__global__ void normalize_kernel() {
    const int u = blockIdx.x * 256 + threadIdx.x;   // uint4 index
    const int hl = u * 8;
    const int bh = hl >> 11;            // b*64 + h
    const int s = hl & (TT - 1);
    const float* Zp = g_sum + ((bh >> 6) << 11) + s;
    uint4 val = *(uint4*)&g_vT[(size_t)bh * TT + s];
    __half2* hp = (__half2*)&val;
    const float4 z0 = *(const float4*)&Zp[0];
    const float4 z1 = *(const float4*)&Zp[4];
    float2 f;
    f = __half22float2(hp[0]);
    hp[0] = __floats2half2_rn(f.x * __frcp_rn(z0.x), f.y * __frcp_rn(z0.y));
    f = __half22float2(hp[1]);
    hp[1] = __floats2half2_rn(f.x * __frcp_rn(z0.z), f.y * __frcp_rn(z0.w));
    f = __half22float2(hp[2]);
    hp[2] = __floats2half2_rn(f.x * __frcp_rn(z1.x), f.y * __frcp_rn(z1.y));
    f = __half22float2(hp[3]);
    hp[3] = __floats2half2_rn(f.x * __frcp_rn(z1.z), f.y * __frcp_rn(z1.w));
    *(uint4*)&g_vT[(size_t)bh * TT + s] = val;
}

// ---------------------------------------------------------------------------
// pv tile fill: pure uint4 copies.
// ---------------------------------------------------------------------------
__device__ __forceinline__ void fill_pv(const __half* __restrict__ Pb,
                                        const __half* __restrict__ vTb,
                                        __half* Psb, __half* vsb,
                                        int t0, int s0, int tid) {
#pragma unroll
    for (int i = tid; i < 512; i += 256) {
        int r = i >> 3, j = (i & 7) * 8;
        *(uint4*)&Psb[r * HS + j] = *(const uint4*)&Pb[(size_t)(t0 + r) * TT + s0 + j];
        *(uint4*)&vsb[r * HS + j] = *(const uint4*)&vTb[(size_t)r * TT + s0 + j];
    }
}

// ---------------------------------------------------------------------------
// Kernel 4: out[t][h] += sum_s P[t][s] * vT[h][s] (vT pre-scaled by 1/Z).
// fp16 MMA + ldmatrix. A = P (row-major), B = vT (col-major [h][s]).
// grid = (T/64, 8 s-chunks of 4 tiles, B), block 256, dyn smem 36864B.
// Warps: 4 t-groups (16 rows) x 2 h-groups (32 cols). Double buffered.
// ---------------------------------------------------------------------------
__global__ void __launch_bounds__(256, 2) pv_kernel(float* __restrict__ out) {
    const int tt = blockIdx.x;
    const int chunk0 = blockIdx.y * 4;
    if (chunk0 > tt) return;
    const int t0 = tt * 64;
    const int b = blockIdx.z;
    const __half* Pb = g_Ph + (size_t)b * TT * TT;
    const __half* vTb = g_vT + (size_t)b * HH * TT;
    extern __shared__ __align__(16) __half sm[];
    __half* Ps = sm;              // 2 x [64][HS]
    __half* vs = sm + 2 * 64 * HS;
    const int tid = threadIdx.x;
    const int lane = tid & 31, wid = tid >> 5;
    const int g = lane >> 2, tg = lane & 3;
    const int tw = (wid >> 1) * 16;
    const int hw = (wid & 1) * 32;

    unsigned aab, bab[2];
    {
        const int ar = A_OFF(lane), ak = A_KOFF(lane);
        const int br = B_OFF(lane), bk = B_KOFF(lane);
        aab = smaddr(&Ps[(tw + ar) * HS + ak]);
        bab[0] = smaddr(&vs[(hw + br) * HS + bk]);
        bab[1] = smaddr(&vs[(hw + 16 + br) * HS + bk]);
    }
    const unsigned bufstep = 64 * HS * 2;  // bytes per buffer

    float acc[4][4] = {};  // [nt(h)][4]
    const int st_end = min(chunk0 + 4, tt + 1);

    fill_pv(Pb, vTb, Ps, vs, t0, chunk0 * 64, tid);
    for (int st = chunk0; st < st_end; st++) {
        const int buf = (st - chunk0) & 1;
        __syncthreads();
        if (st + 1 < st_end)
            fill_pv(Pb, vTb, Ps + (buf ^ 1) * 64 * HS, vs + (buf ^ 1) * 64 * HS,
                    t0, (st + 1) * 64, tid);
        const unsigned boff = buf * bufstep;
#pragma unroll
        for (int k4 = 0; k4 < 4; k4++) {
            unsigned a[4], bq[2][4];
            ldsm_x4(a, aab + boff + k4 * 32);
            ldsm_x4(bq[0], bab[0] + boff + k4 * 32);
            ldsm_x4(bq[1], bab[1] + boff + k4 * 32);
#pragma unroll
            for (int nt = 0; nt < 4; nt++)
                mma16(acc[nt], a, bq[nt >> 1] + (nt & 1) * 2);
        }
    }

    float* ob = out + (size_t)b * TT * HH;
    const int tr0 = t0 + tw + g, tr1 = tr0 + 8;
#pragma unroll
    for (int nt = 0; nt < 4; nt++) {
        const int h = hw + nt * 8 + 2 * tg;
        atomicAdd(&ob[(size_t)tr0 * HH + h],     acc[nt][0]);
        atomicAdd(&ob[(size_t)tr0 * HH + h + 1], acc[nt][1]);
        atomicAdd(&ob[(size_t)tr1 * HH + h],     acc[nt][2]);
        atomicAdd(&ob[(size_t)tr1 * HH + h + 1], acc[nt][3]);
    }
}

// ---------------------------------------------------------------------------
extern "C" void kernel_launch(void* const* d_in, const int* in_sizes, int n_in,
                              void* d_out, int out_size) {
    const float* x  = (const float*)d_in[0];
    const float* Wq = (const float*)d_in[1];
    const float* Wk = (const float*)d_in[2];
    const float* Wv = (const float*)d_in[3];
    float* out = (float*)d_out;

    const float scale = 1.0f / sqrtf((float)CC);

    cudaFuncSetAttribute(scores_kernel,
                         cudaFuncAttributeMaxDynamicSharedMemorySize, 36864);
    cudaFuncSetAttribute(pv_kernel,
                         cudaFuncAttributeMaxDynamicSharedMemorySize, 36864);

    zero_kernel<<<1024, 256>>>(out);

    dim3 gProj(BB * TT / 64, 3);
    proj_kernel<<<gProj, 256>>>(x, Wq, Wk, Wv);

    dim3 gScores(TT / 128, TT / 128, BB);
    scores_kernel<<<gScores, 256, 36864>>>(scale);

    normalize_kernel<<<512, 256>>>();

    dim3 gPV(TT / 64, 8, BB);
    pv_kernel<<<gPV, 256, 36864>>>(out);
}

// round 14
// speedup vs baseline: 2.5524x; 1.0578x over previous
#include <cuda_runtime.h>
#include <cuda_fp16.h>
#include <math.h>

#define BB 8
#define TT 2048
#define CC 384
#define HH 64

// Scratch (allocation-free rule: __device__ globals)
__device__ __half g_qh[BB * TT * HH];               // 2 MB  [b][t][h]
__device__ __half g_kh[BB * TT * HH];               // 2 MB  [b][s][h]
__device__ __half g_vT[BB * HH * TT];               // 2 MB  [b][h][s], later scaled 1/Z
__device__ float  g_sum[BB * TT];                   // per-key exp sums
__device__ __half g_Ph[(size_t)BB * TT * TT];       // 67 MB unnormalized exp, [b][t][s]

// ---------------------------------------------------------------------------
// fp16 m16n8k16 MMA + ldmatrix helpers. g = lane>>2, tg = lane&3.
//  A row-major [m][k]: a0=(g,2tg) a1=(g+8,2tg) a2=(g,2tg+8) a3=(g+8,2tg+8)
//  B col-major [n][k]: b0=(n g, k 2tg) b1=(n g, k 2tg+8)
//  C: c0=(g,2tg) c1=(g,2tg+1) c2=(g+8,2tg) c3=(g+8,2tg+1)
// ---------------------------------------------------------------------------
__device__ __forceinline__ void mma16(float* c, const unsigned* a, const unsigned* b) {
    asm("mma.sync.aligned.m16n8k16.row.col.f32.f16.f16.f32 "
        "{%0,%1,%2,%3},{%4,%5,%6,%7},{%8,%9},{%0,%1,%2,%3};"
        : "+f"(c[0]), "+f"(c[1]), "+f"(c[2]), "+f"(c[3])
        : "r"(a[0]), "r"(a[1]), "r"(a[2]), "r"(a[3]), "r"(b[0]), "r"(b[1]));
}

__device__ __forceinline__ void ldsm_x4(unsigned* r, unsigned addr) {
    asm volatile("ldmatrix.sync.aligned.m8n8.x4.shared.b16 {%0,%1,%2,%3}, [%4];"
                 : "=r"(r[0]), "=r"(r[1]), "=r"(r[2]), "=r"(r[3]) : "r"(addr));
}

__device__ __forceinline__ unsigned smaddr(const void* p) {
    return (unsigned)__cvta_generic_to_shared(p);
}

// A-operand x4 base (16 rows x 16 k): matrices (r0,k0),(r+8,k0),(r0,k+8),(r+8,k+8)
#define A_OFF(lane) ((((lane) & 7) + (((lane) >> 3) & 1) * 8) )
#define A_KOFF(lane) ((((lane) >> 4) & 1) * 8)
// B-operand x4 base (16 n-rows x 16 k): matrices (n0,k0),(n0,k+8),(n+8,k0),(n+8,k+8)
#define B_OFF(lane) ((((lane) & 7) + (((lane) >> 4) & 1) * 8))
#define B_KOFF(lane) ((((lane) >> 3) & 1) * 8)

#define HS 72   // half stride for 64-col k tiles (144 B rows, 16B aligned, cf)
#define PS 40   // half stride for 32-col k tiles (80 B rows, 16B aligned, cf)
#define QS 136  // half stride for staged 128-col P tile (272 B rows, 16B aligned)

// ---------------------------------------------------------------------------
// Kernel 1: fused projections, fp16 MMA. Also zeroes g_sum (first 64 y==0
// blocks) so scores can atomicAdd. q -> g_qh[t][h], k -> g_kh[s][h],
// v -> g_vT[h][s] (transposed). grid = (B*T/64, 3), block = 256.
// ---------------------------------------------------------------------------
__global__ void proj_kernel(const float* __restrict__ x,
                            const float* __restrict__ Wq,
                            const float* __restrict__ Wk,
                            const float* __restrict__ Wv) {
    __shared__ __align__(16) __half xs[64 * PS];  // [m][k32]
    __shared__ __align__(16) __half ws[64 * PS];  // [n][k32] (W transposed)
    const int tid = threadIdx.x;
    if (blockIdx.y == 0 && blockIdx.x < 64)
        g_sum[blockIdx.x * 256 + tid] = 0.f;
    const float* W = (blockIdx.y == 0) ? Wq : (blockIdx.y == 1) ? Wk : Wv;
    const int row0 = blockIdx.x * 64;
    const int lane = tid & 31, wid = tid >> 5;
    const int g = lane >> 2, tg = lane & 3;
    const int mw = (wid & 1) * 32, nw = (wid >> 1) * 16;

    unsigned aab[2], bab;
    {
        const int ar = A_OFF(lane), ak = A_KOFF(lane);
        aab[0] = smaddr(&xs[(mw + ar) * PS + ak]);
        aab[1] = smaddr(&xs[(mw + 16 + ar) * PS + ak]);
        bab = smaddr(&ws[(nw + B_OFF(lane)) * PS + B_KOFF(lane)]);
    }

    float acc[2][2][4] = {};
    for (int k0c = 0; k0c < CC; k0c += 32) {
#pragma unroll
        for (int i = tid; i < 512; i += 256) {   // x: 64 m x 32 k
            int r = i >> 3, c4 = (i & 7) * 4;
            float4 v = *(const float4*)&x[(size_t)(row0 + r) * CC + k0c + c4];
            *(__half2*)&xs[r * PS + c4]     = __floats2half2_rn(v.x, v.y);
            *(__half2*)&xs[r * PS + c4 + 2] = __floats2half2_rn(v.z, v.w);
        }
#pragma unroll
        for (int i = tid; i < 512; i += 256) {   // W: 32 k x 64 n -> transpose
            int r = i >> 4, c4 = (i & 15) * 4;
            float4 v = *(const float4*)&W[(k0c + r) * HH + c4];
            ws[(c4 + 0) * PS + r] = __float2half(v.x);
            ws[(c4 + 1) * PS + r] = __float2half(v.y);
            ws[(c4 + 2) * PS + r] = __float2half(v.z);
            ws[(c4 + 3) * PS + r] = __float2half(v.w);
        }
        __syncthreads();
#pragma unroll
        for (int kk = 0; kk < 2; kk++) {         // two k16 steps
            unsigned a[2][4], bq[4];
            ldsm_x4(a[0], aab[0] + kk * 32);
            ldsm_x4(a[1], aab[1] + kk * 32);
            ldsm_x4(bq, bab + kk * 32);
#pragma unroll
            for (int mt = 0; mt < 2; mt++)
#pragma unroll
                for (int nt = 0; nt < 2; nt++)
                    mma16(acc[mt][nt], a[mt], bq + nt * 2);
        }
        __syncthreads();
    }

    __half* outqk = (blockIdx.y == 0) ? g_qh : g_kh;
#pragma unroll
    for (int mt = 0; mt < 2; mt++)
#pragma unroll
        for (int rs = 0; rs < 2; rs++) {
            const int row = row0 + mw + mt * 16 + rs * 8 + g;
#pragma unroll
            for (int nt = 0; nt < 2; nt++) {
                const int col = nw + nt * 8 + 2 * tg;
                const float v0 = acc[mt][nt][rs * 2], v1 = acc[mt][nt][rs * 2 + 1];
                if (blockIdx.y < 2) {
                    *(__half2*)&outqk[(size_t)row * HH + col] = __floats2half2_rn(v0, v1);
                } else {
                    const int s = row & (TT - 1);
                    const size_t hb = (size_t)(row >> 11) * HH;
                    g_vT[(hb + col) * TT + s]     = __float2half(v0);
                    g_vT[(hb + col + 1) * TT + s] = __float2half(v1);
                }
            }
        }
}

// ---------------------------------------------------------------------------
// Kernel 2: scores, fp16 MMA + ldmatrix, 128x128 tiles. P[t][s] = exp (half,
// 0 where t<s); Z[s] += row sums. m=t, n=s, k=h.
// Epilogue stages P in smem (reusing the q/k tiles) and writes coalesced
// uint4 rows. grid = (T/128, T/128, B), block 256, dyn smem 36864B.
// Warps: 2 t-groups (64 rows) x 4 s-groups (32 cols).
// ---------------------------------------------------------------------------
__global__ void __launch_bounds__(256, 2) scores_kernel(float scale) {
    const int t0 = blockIdx.x * 128;
    const int s0 = blockIdx.y * 128;
    if (t0 + 127 < s0) return;
    const int b = blockIdx.z;
    extern __shared__ __align__(16) __half sm[];
    __half* qs = sm;              // [128][HS]
    __half* ks = sm + 128 * HS;   // [128][HS]
    const __half* qb = g_qh + (size_t)b * TT * HH;
    const __half* kb = g_kh + (size_t)b * TT * HH;
    const int tid = threadIdx.x;
#pragma unroll
    for (int i = tid; i < 1024; i += 256) {
        int r = i >> 3, j = (i & 7) * 8;
        *(uint4*)&qs[r * HS + j] = *(const uint4*)&qb[(size_t)(t0 + r) * HH + j];
        *(uint4*)&ks[r * HS + j] = *(const uint4*)&kb[(size_t)(s0 + r) * HH + j];
    }
    __syncthreads();
    const int lane = tid & 31, wid = tid >> 5;
    const int g = lane >> 2, tg = lane & 3;
    const int tw = (wid & 1) * 64, sw = (wid >> 1) * 32;

    unsigned aab[4], bab[2];
    {
        const int ar = A_OFF(lane), ak = A_KOFF(lane);
        const int br = B_OFF(lane), bk = B_KOFF(lane);
#pragma unroll
        for (int mt = 0; mt < 4; mt++)
            aab[mt] = smaddr(&qs[(tw + mt * 16 + ar) * HS + ak]);
#pragma unroll
        for (int np = 0; np < 2; np++)
            bab[np] = smaddr(&ks[(sw + np * 16 + br) * HS + bk]);
    }

    float acc[4][4][4] = {};  // [mt(t)][nt(s)][4]
#pragma unroll
    for (int k4 = 0; k4 < 4; k4++) {
        unsigned a[4][4], bq[2][4];
#pragma unroll
        for (int mt = 0; mt < 4; mt++) ldsm_x4(a[mt], aab[mt] + k4 * 32);
#pragma unroll
        for (int np = 0; np < 2; np++) ldsm_x4(bq[np], bab[np] + k4 * 32);
#pragma unroll
        for (int mt = 0; mt < 4; mt++)
#pragma unroll
            for (int nt = 0; nt < 4; nt++)
                mma16(acc[mt][nt], a[mt], bq[nt >> 1] + (nt & 1) * 2);
    }
    __syncthreads();  // q/k tiles dead; reuse smem to stage P

    // Epilogue: exp + mask into staged smem P tile [128][QS]; Z partial sums.
    __half* Pst = sm;
    float* Zb = g_sum + b * TT;
    float zc[4][2] = {};
#pragma unroll
    for (int mt = 0; mt < 4; mt++)
#pragma unroll
        for (int rs = 0; rs < 2; rs++) {
            const int tl = tw + mt * 16 + rs * 8 + g;
            const int t = t0 + tl;
#pragma unroll
            for (int nt = 0; nt < 4; nt++) {
                const int sl = sw + nt * 8 + 2 * tg;
                const int s = s0 + sl;
                float e0 = (t >= s) ? __expf(acc[mt][nt][rs * 2] * scale)     : 0.f;
                float e1 = (t >  s) ? __expf(acc[mt][nt][rs * 2 + 1] * scale) : 0.f;
                *(__half2*)&Pst[tl * QS + sl] = __floats2half2_rn(e0, e1);
                zc[nt][0] += e0; zc[nt][1] += e1;
            }
        }
#pragma unroll
    for (int nt = 0; nt < 4; nt++) {
        float z0 = zc[nt][0], z1 = zc[nt][1];
#pragma unroll
        for (int o = 4; o < 32; o <<= 1) {
            z0 += __shfl_xor_sync(0xffffffffu, z0, o);
            z1 += __shfl_xor_sync(0xffffffffu, z1, o);
        }
        if (g == 0) {
            const int s = s0 + sw + nt * 8 + 2 * tg;
            atomicAdd(&Zb[s], z0);
            atomicAdd(&Zb[s + 1], z1);
        }
    }
    __syncthreads();  // P staged

    // Coalesced write: 128 rows x 256B, uint4 per thread-iter.
    __half* Pb = g_Ph + (size_t)b * TT * TT;
#pragma unroll
    for (int i = tid; i < 2048; i += 256) {
        int r = i >> 4, c = (i & 15) * 8;
        *(uint4*)&Pb[(size_t)(t0 + r) * TT + s0 + c] = *(const uint4*)&Pst[r * QS + c];
    }
}

// ---------------------------------------------------------------------------
// Kernel 3: scale vT in place by 1/Z[s]; also zeroes d_out for pv's atomics.
// grid = 512, block = 256 (one uint4 = 8 halves per thread).
// ---------------------------------------------------------------------------
__global__ void normalize_kernel(float* __restrict__ out) {
    const int u = blockIdx.x * 256 + threadIdx.x;   // uint4 index
    const float4 z = make_float4(0.f, 0.f, 0.f, 0.f);
    ((float4*)out)[u * 2]     = z;
    ((float4*)out)[u * 2 + 1] = z;
    const int hl = u * 8;
    const int bh = hl >> 11;            // b*64 + h
    const int s = hl & (TT - 1);
    const float* Zp = g_sum + ((bh >> 6) << 11) + s;
    uint4 val = *(uint4*)&g_vT[(size_t)bh * TT + s];
    __half2* hp = (__half2*)&val;
    const float4 z0 = *(const float4*)&Zp[0];
    const float4 z1 = *(const float4*)&Zp[4];
    float2 f;
    f = __half22float2(hp[0]);
    hp[0] = __floats2half2_rn(f.x * __frcp_rn(z0.x), f.y * __frcp_rn(z0.y));
    f = __half22float2(hp[1]);
    hp[1] = __floats2half2_rn(f.x * __frcp_rn(z0.z), f.y * __frcp_rn(z0.w));
    f = __half22float2(hp[2]);
    hp[2] = __floats2half2_rn(f.x * __frcp_rn(z1.x), f.y * __frcp_rn(z1.y));
    f = __half22float2(hp[3]);
    hp[3] = __floats2half2_rn(f.x * __frcp_rn(z1.z), f.y * __frcp_rn(z1.w));
    *(uint4*)&g_vT[(size_t)bh * TT + s] = val;
}

// ---------------------------------------------------------------------------
// pv tile fill: pure uint4 copies.
// ---------------------------------------------------------------------------
__device__ __forceinline__ void fill_pv(const __half* __restrict__ Pb,
                                        const __half* __restrict__ vTb,
                                        __half* Psb, __half* vsb,
                                        int t0, int s0, int tid) {
#pragma unroll
    for (int i = tid; i < 512; i += 256) {
        int r = i >> 3, j = (i & 7) * 8;
        *(uint4*)&Psb[r * HS + j] = *(const uint4*)&Pb[(size_t)(t0 + r) * TT + s0 + j];
        *(uint4*)&vsb[r * HS + j] = *(const uint4*)&vTb[(size_t)r * TT + s0 + j];
    }
}

// ---------------------------------------------------------------------------
// Kernel 4: out[t][h] += sum_s P[t][s] * vT[h][s] (vT pre-scaled by 1/Z).
// fp16 MMA + ldmatrix, double buffered. s-chunks of 8 tiles (fewer blocks,
// half the atomic traffic vs 4). grid = (T/64, 4, B), block 256, smem 36864B.
// Warps: 4 t-groups (16 rows) x 2 h-groups (32 cols).
// ---------------------------------------------------------------------------
__global__ void __launch_bounds__(256, 2) pv_kernel(float* __restrict__ out) {
    const int tt = blockIdx.x;
    const int chunk0 = blockIdx.y * 8;
    if (chunk0 > tt) return;
    const int t0 = tt * 64;
    const int b = blockIdx.z;
    const __half* Pb = g_Ph + (size_t)b * TT * TT;
    const __half* vTb = g_vT + (size_t)b * HH * TT;
    extern __shared__ __align__(16) __half sm[];
    __half* Ps = sm;              // 2 x [64][HS]
    __half* vs = sm + 2 * 64 * HS;
    const int tid = threadIdx.x;
    const int lane = tid & 31, wid = tid >> 5;
    const int g = lane >> 2, tg = lane & 3;
    const int tw = (wid >> 1) * 16;
    const int hw = (wid & 1) * 32;

    unsigned aab, bab[2];
    {
        const int ar = A_OFF(lane), ak = A_KOFF(lane);
        const int br = B_OFF(lane), bk = B_KOFF(lane);
        aab = smaddr(&Ps[(tw + ar) * HS + ak]);
        bab[0] = smaddr(&vs[(hw + br) * HS + bk]);
        bab[1] = smaddr(&vs[(hw + 16 + br) * HS + bk]);
    }
    const unsigned bufstep = 64 * HS * 2;  // bytes per buffer

    float acc[4][4] = {};  // [nt(h)][4]
    const int st_end = min(chunk0 + 8, tt + 1);

    fill_pv(Pb, vTb, Ps, vs, t0, chunk0 * 64, tid);
    for (int st = chunk0; st < st_end; st++) {
        const int buf = (st - chunk0) & 1;
        __syncthreads();
        if (st + 1 < st_end)
            fill_pv(Pb, vTb, Ps + (buf ^ 1) * 64 * HS, vs + (buf ^ 1) * 64 * HS,
                    t0, (st + 1) * 64, tid);
        const unsigned boff = buf * bufstep;
#pragma unroll
        for (int k4 = 0; k4 < 4; k4++) {
            unsigned a[4], bq[2][4];
            ldsm_x4(a, aab + boff + k4 * 32);
            ldsm_x4(bq[0], bab[0] + boff + k4 * 32);
            ldsm_x4(bq[1], bab[1] + boff + k4 * 32);
#pragma unroll
            for (int nt = 0; nt < 4; nt++)
                mma16(acc[nt], a, bq[nt >> 1] + (nt & 1) * 2);
        }
    }

    float* ob = out + (size_t)b * TT * HH;
    const int tr0 = t0 + tw + g, tr1 = tr0 + 8;
#pragma unroll
    for (int nt = 0; nt < 4; nt++) {
        const int h = hw + nt * 8 + 2 * tg;
        atomicAdd(&ob[(size_t)tr0 * HH + h],     acc[nt][0]);
        atomicAdd(&ob[(size_t)tr0 * HH + h + 1], acc[nt][1]);
        atomicAdd(&ob[(size_t)tr1 * HH + h],     acc[nt][2]);
        atomicAdd(&ob[(size_t)tr1 * HH + h + 1], acc[nt][3]);
    }
}

// ---------------------------------------------------------------------------
extern "C" void kernel_launch(void* const* d_in, const int* in_sizes, int n_in,
                              void* d_out, int out_size) {
    const float* x  = (const float*)d_in[0];
    const float* Wq = (const float*)d_in[1];
    const float* Wk = (const float*)d_in[2];
    const float* Wv = (const float*)d_in[3];
    float* out = (float*)d_out;

    const float scale = 1.0f / sqrtf((float)CC);

    cudaFuncSetAttribute(scores_kernel,
                         cudaFuncAttributeMaxDynamicSharedMemorySize, 36864);
    cudaFuncSetAttribute(pv_kernel,
                         cudaFuncAttributeMaxDynamicSharedMemorySize, 36864);

    dim3 gProj(BB * TT / 64, 3);
    proj_kernel<<<gProj, 256>>>(x, Wq, Wk, Wv);

    dim3 gScores(TT / 128, TT / 128, BB);
    scores_kernel<<<gScores, 256, 36864>>>(scale);

    normalize_kernel<<<512, 256>>>(out);

    dim3 gPV(TT / 64, 4, BB);
    pv_kernel<<<gPV, 256, 36864>>>(out);
}

// round 15
// speedup vs baseline: 2.6425x; 1.0353x over previous
#include <cuda_runtime.h>
#include <cuda_fp16.h>
#include <math.h>

#define BB 8
#define TT 2048
#define CC 384
#define HH 64

// Scratch (allocation-free rule: __device__ globals)
__device__ __half g_qh[BB * TT * HH];               // 2 MB  [b][t][h]
__device__ __half g_kh[BB * TT * HH];               // 2 MB  [b][s][h]
__device__ __half g_vT[BB * HH * TT];               // 2 MB  [b][h][s], later scaled 1/Z
__device__ float  g_sum[BB * TT];                   // per-key exp sums
__device__ __half g_Ph[(size_t)BB * TT * TT];       // 67 MB unnormalized exp, [b][t][s]

// ---------------------------------------------------------------------------
// fp16 m16n8k16 MMA + ldmatrix + cp.async helpers. g = lane>>2, tg = lane&3.
//  A row-major [m][k]: a0=(g,2tg) a1=(g+8,2tg) a2=(g,2tg+8) a3=(g+8,2tg+8)
//  B col-major [n][k]: b0=(n g, k 2tg) b1=(n g, k 2tg+8)
//  C: c0=(g,2tg) c1=(g,2tg+1) c2=(g+8,2tg) c3=(g+8,2tg+1)
// ---------------------------------------------------------------------------
__device__ __forceinline__ void mma16(float* c, const unsigned* a, const unsigned* b) {
    asm("mma.sync.aligned.m16n8k16.row.col.f32.f16.f16.f32 "
        "{%0,%1,%2,%3},{%4,%5,%6,%7},{%8,%9},{%0,%1,%2,%3};"
        : "+f"(c[0]), "+f"(c[1]), "+f"(c[2]), "+f"(c[3])
        : "r"(a[0]), "r"(a[1]), "r"(a[2]), "r"(a[3]), "r"(b[0]), "r"(b[1]));
}

__device__ __forceinline__ void ldsm_x4(unsigned* r, unsigned addr) {
    asm volatile("ldmatrix.sync.aligned.m8n8.x4.shared.b16 {%0,%1,%2,%3}, [%4];"
                 : "=r"(r[0]), "=r"(r[1]), "=r"(r[2]), "=r"(r[3]) : "r"(addr));
}

__device__ __forceinline__ unsigned smaddr(const void* p) {
    return (unsigned)__cvta_generic_to_shared(p);
}

__device__ __forceinline__ void cp16(unsigned dst, const void* src) {
    asm volatile("cp.async.cg.shared.global [%0], [%1], 16;" :: "r"(dst), "l"(src));
}
#define CP_COMMIT() asm volatile("cp.async.commit_group;")
#define CP_WAIT0()  asm volatile("cp.async.wait_group 0;")
#define CP_WAIT1()  asm volatile("cp.async.wait_group 1;")

// A-operand x4 base (16 rows x 16 k): matrices (r0,k0),(r+8,k0),(r0,k+8),(r+8,k+8)
#define A_OFF(lane) ((((lane) & 7) + (((lane) >> 3) & 1) * 8) )
#define A_KOFF(lane) ((((lane) >> 4) & 1) * 8)
// B-operand x4 base (16 n-rows x 16 k): matrices (n0,k0),(n0,k+8),(n+8,k0),(n+8,k+8)
#define B_OFF(lane) ((((lane) & 7) + (((lane) >> 4) & 1) * 8))
#define B_KOFF(lane) ((((lane) >> 3) & 1) * 8)

#define HS 72   // half stride for 64-col k tiles (144 B rows, 16B aligned, cf)
#define PS 40   // half stride for 32-col k tiles (80 B rows, 16B aligned, cf)
#define QS 136  // half stride for staged 128-col P tile (272 B rows, 16B aligned)

// ---------------------------------------------------------------------------
// Kernel 1: fused projections, fp16 MMA. Also zeroes g_sum (first 64 y==0
// blocks). q -> g_qh[t][h], k -> g_kh[s][h], v -> g_vT[h][s].
// grid = (B*T/64, 3), block = 256.
// ---------------------------------------------------------------------------
__global__ void proj_kernel(const float* __restrict__ x,
                            const float* __restrict__ Wq,
                            const float* __restrict__ Wk,
                            const float* __restrict__ Wv) {
    __shared__ __align__(16) __half xs[64 * PS];  // [m][k32]
    __shared__ __align__(16) __half ws[64 * PS];  // [n][k32] (W transposed)
    const int tid = threadIdx.x;
    if (blockIdx.y == 0 && blockIdx.x < 64)
        g_sum[blockIdx.x * 256 + tid] = 0.f;
    const float* W = (blockIdx.y == 0) ? Wq : (blockIdx.y == 1) ? Wk : Wv;
    const int row0 = blockIdx.x * 64;
    const int lane = tid & 31, wid = tid >> 5;
    const int g = lane >> 2, tg = lane & 3;
    const int mw = (wid & 1) * 32, nw = (wid >> 1) * 16;

    unsigned aab[2], bab;
    {
        const int ar = A_OFF(lane), ak = A_KOFF(lane);
        aab[0] = smaddr(&xs[(mw + ar) * PS + ak]);
        aab[1] = smaddr(&xs[(mw + 16 + ar) * PS + ak]);
        bab = smaddr(&ws[(nw + B_OFF(lane)) * PS + B_KOFF(lane)]);
    }

    float acc[2][2][4] = {};
    for (int k0c = 0; k0c < CC; k0c += 32) {
#pragma unroll
        for (int i = tid; i < 512; i += 256) {   // x: 64 m x 32 k
            int r = i >> 3, c4 = (i & 7) * 4;
            float4 v = *(const float4*)&x[(size_t)(row0 + r) * CC + k0c + c4];
            *(__half2*)&xs[r * PS + c4]     = __floats2half2_rn(v.x, v.y);
            *(__half2*)&xs[r * PS + c4 + 2] = __floats2half2_rn(v.z, v.w);
        }
#pragma unroll
        for (int i = tid; i < 512; i += 256) {   // W: 32 k x 64 n -> transpose
            int r = i >> 4, c4 = (i & 15) * 4;
            float4 v = *(const float4*)&W[(k0c + r) * HH + c4];
            ws[(c4 + 0) * PS + r] = __float2half(v.x);
            ws[(c4 + 1) * PS + r] = __float2half(v.y);
            ws[(c4 + 2) * PS + r] = __float2half(v.z);
            ws[(c4 + 3) * PS + r] = __float2half(v.w);
        }
        __syncthreads();
#pragma unroll
        for (int kk = 0; kk < 2; kk++) {         // two k16 steps
            unsigned a[2][4], bq[4];
            ldsm_x4(a[0], aab[0] + kk * 32);
            ldsm_x4(a[1], aab[1] + kk * 32);
            ldsm_x4(bq, bab + kk * 32);
#pragma unroll
            for (int mt = 0; mt < 2; mt++)
#pragma unroll
                for (int nt = 0; nt < 2; nt++)
                    mma16(acc[mt][nt], a[mt], bq + nt * 2);
        }
        __syncthreads();
    }

    __half* outqk = (blockIdx.y == 0) ? g_qh : g_kh;
#pragma unroll
    for (int mt = 0; mt < 2; mt++)
#pragma unroll
        for (int rs = 0; rs < 2; rs++) {
            const int row = row0 + mw + mt * 16 + rs * 8 + g;
#pragma unroll
            for (int nt = 0; nt < 2; nt++) {
                const int col = nw + nt * 8 + 2 * tg;
                const float v0 = acc[mt][nt][rs * 2], v1 = acc[mt][nt][rs * 2 + 1];
                if (blockIdx.y < 2) {
                    *(__half2*)&outqk[(size_t)row * HH + col] = __floats2half2_rn(v0, v1);
                } else {
                    const int s = row & (TT - 1);
                    const size_t hb = (size_t)(row >> 11) * HH;
                    g_vT[(hb + col) * TT + s]     = __float2half(v0);
                    g_vT[(hb + col + 1) * TT + s] = __float2half(v1);
                }
            }
        }
}

// ---------------------------------------------------------------------------
// Kernel 2: scores, fp16 MMA + ldmatrix, 128x128 tiles, cp.async fills.
// P[t][s] = exp (half, 0 where t<s); Z[s] += row sums. m=t, n=s, k=h.
// Epilogue stages P in smem, writes coalesced uint4 rows.
// grid = (T/128, T/128, B), block 256, dyn smem 36864B (2 blocks/SM).
// ---------------------------------------------------------------------------
__global__ void __launch_bounds__(256, 2) scores_kernel(float scale) {
    const int t0 = blockIdx.x * 128;
    const int s0 = blockIdx.y * 128;
    if (t0 + 127 < s0) return;
    const int b = blockIdx.z;
    extern __shared__ __align__(16) __half sm[];
    __half* qs = sm;              // [128][HS]
    __half* ks = sm + 128 * HS;   // [128][HS]
    const __half* qb = g_qh + (size_t)b * TT * HH;
    const __half* kb = g_kh + (size_t)b * TT * HH;
    const int tid = threadIdx.x;
    const unsigned qsa = smaddr(qs), ksa = smaddr(ks);
#pragma unroll
    for (int i = tid; i < 1024; i += 256) {
        int r = i >> 3, j = (i & 7) * 8;
        cp16(qsa + (r * HS + j) * 2, &qb[(size_t)(t0 + r) * HH + j]);
        cp16(ksa + (r * HS + j) * 2, &kb[(size_t)(s0 + r) * HH + j]);
    }
    CP_COMMIT();
    CP_WAIT0();
    __syncthreads();
    const int lane = tid & 31, wid = tid >> 5;
    const int g = lane >> 2, tg = lane & 3;
    const int tw = (wid & 1) * 64, sw = (wid >> 1) * 32;

    unsigned aab[4], bab[2];
    {
        const int ar = A_OFF(lane), ak = A_KOFF(lane);
        const int br = B_OFF(lane), bk = B_KOFF(lane);
#pragma unroll
        for (int mt = 0; mt < 4; mt++)
            aab[mt] = smaddr(&qs[(tw + mt * 16 + ar) * HS + ak]);
#pragma unroll
        for (int np = 0; np < 2; np++)
            bab[np] = smaddr(&ks[(sw + np * 16 + br) * HS + bk]);
    }

    float acc[4][4][4] = {};  // [mt(t)][nt(s)][4]
#pragma unroll
    for (int k4 = 0; k4 < 4; k4++) {
        unsigned a[4][4], bq[2][4];
#pragma unroll
        for (int mt = 0; mt < 4; mt++) ldsm_x4(a[mt], aab[mt] + k4 * 32);
#pragma unroll
        for (int np = 0; np < 2; np++) ldsm_x4(bq[np], bab[np] + k4 * 32);
#pragma unroll
        for (int mt = 0; mt < 4; mt++)
#pragma unroll
            for (int nt = 0; nt < 4; nt++)
                mma16(acc[mt][nt], a[mt], bq[nt >> 1] + (nt & 1) * 2);
    }
    __syncthreads();  // q/k tiles dead; reuse smem to stage P

    // Epilogue: exp + mask into staged smem P tile [128][QS]; Z partial sums.
    __half* Pst = sm;
    float* Zb = g_sum + b * TT;
    float zc[4][2] = {};
#pragma unroll
    for (int mt = 0; mt < 4; mt++)
#pragma unroll
        for (int rs = 0; rs < 2; rs++) {
            const int tl = tw + mt * 16 + rs * 8 + g;
            const int t = t0 + tl;
#pragma unroll
            for (int nt = 0; nt < 4; nt++) {
                const int sl = sw + nt * 8 + 2 * tg;
                const int s = s0 + sl;
                float e0 = (t >= s) ? __expf(acc[mt][nt][rs * 2] * scale)     : 0.f;
                float e1 = (t >  s) ? __expf(acc[mt][nt][rs * 2 + 1] * scale) : 0.f;
                *(__half2*)&Pst[tl * QS + sl] = __floats2half2_rn(e0, e1);
                zc[nt][0] += e0; zc[nt][1] += e1;
            }
        }
#pragma unroll
    for (int nt = 0; nt < 4; nt++) {
        float z0 = zc[nt][0], z1 = zc[nt][1];
#pragma unroll
        for (int o = 4; o < 32; o <<= 1) {
            z0 += __shfl_xor_sync(0xffffffffu, z0, o);
            z1 += __shfl_xor_sync(0xffffffffu, z1, o);
        }
        if (g == 0) {
            const int s = s0 + sw + nt * 8 + 2 * tg;
            atomicAdd(&Zb[s], z0);
            atomicAdd(&Zb[s + 1], z1);
        }
    }
    __syncthreads();  // P staged

    // Coalesced write: 128 rows x 256B, uint4 per thread-iter.
    __half* Pb = g_Ph + (size_t)b * TT * TT;
#pragma unroll
    for (int i = tid; i < 2048; i += 256) {
        int r = i >> 4, c = (i & 15) * 8;
        *(uint4*)&Pb[(size_t)(t0 + r) * TT + s0 + c] = *(const uint4*)&Pst[r * QS + c];
    }
}

// ---------------------------------------------------------------------------
// Kernel 3: scale vT in place by 1/Z[s]; also zeroes d_out for pv's atomics.
// grid = 512, block = 256 (one uint4 = 8 halves per thread).
// ---------------------------------------------------------------------------
__global__ void normalize_kernel(float* __restrict__ out) {
    const int u = blockIdx.x * 256 + threadIdx.x;   // uint4 index
    const float4 z = make_float4(0.f, 0.f, 0.f, 0.f);
    ((float4*)out)[u * 2]     = z;
    ((float4*)out)[u * 2 + 1] = z;
    const int hl = u * 8;
    const int bh = hl >> 11;            // b*64 + h
    const int s = hl & (TT - 1);
    const float* Zp = g_sum + ((bh >> 6) << 11) + s;
    uint4 val = *(uint4*)&g_vT[(size_t)bh * TT + s];
    __half2* hp = (__half2*)&val;
    const float4 z0 = *(const float4*)&Zp[0];
    const float4 z1 = *(const float4*)&Zp[4];
    float2 f;
    f = __half22float2(hp[0]);
    hp[0] = __floats2half2_rn(f.x * __frcp_rn(z0.x), f.y * __frcp_rn(z0.y));
    f = __half22float2(hp[1]);
    hp[1] = __floats2half2_rn(f.x * __frcp_rn(z0.z), f.y * __frcp_rn(z0.w));
    f = __half22float2(hp[2]);
    hp[2] = __floats2half2_rn(f.x * __frcp_rn(z1.x), f.y * __frcp_rn(z1.y));
    f = __half22float2(hp[3]);
    hp[3] = __floats2half2_rn(f.x * __frcp_rn(z1.z), f.y * __frcp_rn(z1.w));
    *(uint4*)&g_vT[(size_t)bh * TT + s] = val;
}

// ---------------------------------------------------------------------------
// pv async tile fill: cp.async 16B, no register round-trip.
// ---------------------------------------------------------------------------
__device__ __forceinline__ void fill_pv_async(const __half* __restrict__ Pb,
                                              const __half* __restrict__ vTb,
                                              unsigned Psb, unsigned vsb,
                                              int t0, int s0, int tid) {
#pragma unroll
    for (int i = tid; i < 512; i += 256) {
        int r = i >> 3, j = (i & 7) * 8;
        cp16(Psb + (r * HS + j) * 2, &Pb[(size_t)(t0 + r) * TT + s0 + j]);
        cp16(vsb + (r * HS + j) * 2, &vTb[(size_t)r * TT + s0 + j]);
    }
}

// ---------------------------------------------------------------------------
// Kernel 4: out[t][h] += sum_s P[t][s] * vT[h][s] (vT pre-scaled by 1/Z).
// fp16 MMA + ldmatrix, 3-stage cp.async pipeline, 3 blocks/SM.
// grid = (T/64, 4 s-chunks of 8 tiles, B), block 256, dyn smem 55296B.
// Warps: 4 t-groups (16 rows) x 2 h-groups (32 cols).
// One commit per iteration (possibly empty) keeps wait_group 1 uniform.
// ---------------------------------------------------------------------------
#define PVST 3
__global__ void __launch_bounds__(256, 3) pv_kernel(float* __restrict__ out) {
    const int tt = blockIdx.x;
    const int chunk0 = blockIdx.y * 8;
    if (chunk0 > tt) return;
    const int t0 = tt * 64;
    const int b = blockIdx.z;
    const __half* Pb = g_Ph + (size_t)b * TT * TT;
    const __half* vTb = g_vT + (size_t)b * HH * TT;
    extern __shared__ __align__(16) __half sm[];
    __half* Ps = sm;                    // PVST x [64][HS]
    __half* vs = sm + PVST * 64 * HS;   // PVST x [64][HS]
    const unsigned Psa = smaddr(Ps), vsa = smaddr(vs);
    const unsigned BUF = 64 * HS * 2;   // bytes per stage
    const int tid = threadIdx.x;
    const int lane = tid & 31, wid = tid >> 5;
    const int g = lane >> 2, tg = lane & 3;
    const int tw = (wid >> 1) * 16;
    const int hw = (wid & 1) * 32;

    unsigned aab, bab[2];
    {
        const int ar = A_OFF(lane), ak = A_KOFF(lane);
        const int br = B_OFF(lane), bk = B_KOFF(lane);
        aab = smaddr(&Ps[(tw + ar) * HS + ak]);
        bab[0] = smaddr(&vs[(hw + br) * HS + bk]);
        bab[1] = smaddr(&vs[(hw + 16 + br) * HS + bk]);
    }

    float acc[4][4] = {};  // [nt(h)][4]
    const int n = min(chunk0 + 8, tt + 1) - chunk0;

    fill_pv_async(Pb, vTb, Psa, vsa, t0, chunk0 * 64, tid);
    CP_COMMIT();
    if (n > 1)
        fill_pv_async(Pb, vTb, Psa + BUF, vsa + BUF, t0, (chunk0 + 1) * 64, tid);
    CP_COMMIT();

    for (int st = 0; st < n; st++) {
        CP_WAIT1();
        __syncthreads();
        const unsigned boff = (unsigned)(st % PVST) * BUF;
#pragma unroll
        for (int k4 = 0; k4 < 4; k4++) {
            unsigned a[4], bq[2][4];
            ldsm_x4(a, aab + boff + k4 * 32);
            ldsm_x4(bq[0], bab[0] + boff + k4 * 32);
            ldsm_x4(bq[1], bab[1] + boff + k4 * 32);
#pragma unroll
            for (int nt = 0; nt < 4; nt++)
                mma16(acc[nt], a, bq[nt >> 1] + (nt & 1) * 2);
        }
        if (st + 2 < n) {
            const unsigned foff = (unsigned)((st + 2) % PVST) * BUF;
            fill_pv_async(Pb, vTb, Psa + foff, vsa + foff,
                          t0, (chunk0 + st + 2) * 64, tid);
        }
        CP_COMMIT();
    }

    float* ob = out + (size_t)b * TT * HH;
    const int tr0 = t0 + tw + g, tr1 = tr0 + 8;
#pragma unroll
    for (int nt = 0; nt < 4; nt++) {
        const int h = hw + nt * 8 + 2 * tg;
        atomicAdd(&ob[(size_t)tr0 * HH + h],     acc[nt][0]);
        atomicAdd(&ob[(size_t)tr0 * HH + h + 1], acc[nt][1]);
        atomicAdd(&ob[(size_t)tr1 * HH + h],     acc[nt][2]);
        atomicAdd(&ob[(size_t)tr1 * HH + h + 1], acc[nt][3]);
    }
}

// ---------------------------------------------------------------------------
extern "C" void kernel_launch(void* const* d_in, const int* in_sizes, int n_in,
                              void* d_out, int out_size) {
    const float* x  = (const float*)d_in[0];
    const float* Wq = (const float*)d_in[1];
    const float* Wk = (const float*)d_in[2];
    const float* Wv = (const float*)d_in[3];
    float* out = (float*)d_out;

    const float scale = 1.0f / sqrtf((float)CC);

    cudaFuncSetAttribute(scores_kernel,
                         cudaFuncAttributeMaxDynamicSharedMemorySize, 36864);
    cudaFuncSetAttribute(pv_kernel,
                         cudaFuncAttributeMaxDynamicSharedMemorySize, 55296);

    dim3 gProj(BB * TT / 64, 3);
    proj_kernel<<<gProj, 256>>>(x, Wq, Wk, Wv);

    dim3 gScores(TT / 128, TT / 128, BB);
    scores_kernel<<<gScores, 256, 36864>>>(scale);

    normalize_kernel<<<512, 256>>>(out);

    dim3 gPV(TT / 64, 4, BB);
    pv_kernel<<<gPV, 256, 55296>>>(out);
}